// round 13
// baseline (speedup 1.0000x reference)
#include <cuda_runtime.h>
#include <cuda_fp16.h>
#include <math.h>
#include <stdint.h>

// ---------------------------------------------------------------------------
// Round 13: GEMM+LayerNorm fusion. New gemm_ln (BM=64 x BN=256: CTA owns the
// full E=256 row) does bias+residual+LN in the epilogue via quad-shfl +
// cross-warp smem reduction -> kills 4 ln_k launches and both 268MB pre-LN
// fp32 round-trips. attn0_tc + gemm_h unchanged from R12.
// ---------------------------------------------------------------------------

#define BATCH 2
#define SEQ   1024
#define E     256
#define FIN   64
#define FF    1024
#define WCTX  64
#define NW    (BATCH*SEQ)
#define PADS  (SEQ + WCTX - 1)
#define NT    (NW*WCTX)

#define ATTN_SCALE 0.17677669529663687f

// ---------------- scratch ----------------------------------------------------
__device__ __align__(128) float g_emb32[BATCH*PADS*E];
__device__ __align__(128) float g_x1_32[NT*E];
__device__ __align__(128) float g_x2_32[NT*E];
__device__ __align__(128) float g_t1_32[NW*E];
__device__ __align__(128) float g_t2   [NW*E];
__device__ __align__(128) __half g_in16  [BATCH*SEQ*FIN];
__device__ __align__(128) __half g_embw16[E*FIN];
__device__ __align__(128) __half g_qkvw16[2*3*E*E];
__device__ __align__(128) __half g_aow16 [2*E*E];
__device__ __align__(128) __half g_f1w16 [2*FF*E];
__device__ __align__(128) __half g_f2w16 [2*E*FF];
__device__ __align__(128) __half g_emb16 [BATCH*PADS*E];
__device__ __align__(128) __half g_qkv16 [BATCH*PADS*3*E];
__device__ __align__(128) __half g_octx16[NT*E];
__device__ __align__(128) __half g_x1_16 [NT*E];
__device__ __align__(128) __half g_h16   [NT*FF];
__device__ __align__(128) __half g_x2_16 [NT*E];
__device__ __align__(128) __half g_kv16  [NT*2*E];
__device__ __align__(128) __half g_q1_16 [NW*E];
__device__ __align__(128) __half g_o1_16 [NW*E];
__device__ __align__(128) __half g_t1_16 [NW*E];
__device__ __align__(128) __half g_th16  [NW*FF];

__global__ void conv_k(const float* __restrict__ src, __half* __restrict__ dst,
                       int total) {
    int idx = blockIdx.x * 256 + threadIdx.x;
    if (idx < total) dst[idx] = __float2half(src[idx]);
}

__global__ void zero_pad_k(float* emb32, __half* emb16) {
    int i = blockIdx.x * 256 + threadIdx.x;
    if (i < (WCTX - 1) * E) {
        emb32[i] = 0.f;                 emb16[i] = __float2half(0.f);
        emb32[(size_t)PADS * E + i] = 0.f;
        emb16[(size_t)PADS * E + i] = __float2half(0.f);
    }
}

// ---------------- shared MMA / ldmatrix macros --------------------------------
#define MMA_F16(d, a0, a1, a2, a3, b0, b1) \
  asm volatile("mma.sync.aligned.m16n8k16.row.col.f32.f16.f16.f32 " \
    "{%0,%1,%2,%3}, {%4,%5,%6,%7}, {%8,%9}, {%0,%1,%2,%3};" \
    : "+f"(d[0]), "+f"(d[1]), "+f"(d[2]), "+f"(d[3]) \
    : "r"(a0), "r"(a1), "r"(a2), "r"(a3), "r"(b0), "r"(b1))

#define LDSM_X4(r0, r1, r2, r3, ad) \
  asm volatile("ldmatrix.sync.aligned.m8n8.x4.shared.b16 {%0,%1,%2,%3}, [%4];" \
    : "=r"(r0), "=r"(r1), "=r"(r2), "=r"(r3) : "r"(ad))

#define LDSM_X4T(r0, r1, r2, r3, ad) \
  asm volatile("ldmatrix.sync.aligned.m8n8.x4.trans.shared.b16 {%0,%1,%2,%3}, [%4];" \
    : "=r"(r0), "=r"(r1), "=r"(r2), "=r"(r3) : "r"(ad))

// ---------------- fp16 tensor-core GEMM (R11/R12, unchanged) ------------------
#define T_TSB 16384
#define NSTG 3
#define GEMM_SMEM (2*NSTG*T_TSB)

#define LOAD_TILE(KT_IDX, ST) do {                                            \
    if ((KT_IDX) < KT) {                                                      \
        const unsigned abase_ = smbase + (unsigned)(ST) * T_TSB;              \
        const unsigned bbase_ = smbase + (unsigned)NSTG * T_TSB + (unsigned)(ST) * T_TSB; \
        const __half* Ak_ = A + (size_t)(KT_IDX) * 64;                        \
        const __half* Bk_ = Wt + (size_t)(KT_IDX) * 64;                       \
        _Pragma("unroll")                                                     \
        for (int i_ = 0; i_ < 4; i_++) {                                      \
            const int c_   = tid + 256 * i_;                                  \
            const int row_ = c_ >> 3;                                         \
            const int ch_  = c_ & 7;                                          \
            const unsigned soff_ = (unsigned)(row_ * 128 + ((ch_ ^ (row_ & 7)) * 16)); \
            const int am_  = bm0 + row_;                                      \
            const __half* sa_ = Ak_ + (size_t)(am_ < M ? am_ : 0) * lda + ch_ * 8; \
            const int sz_     = (am_ < M) ? 16 : 0;                           \
            asm volatile("cp.async.cg.shared.global [%0], [%1], 16, %2;" ::   \
                "r"(abase_ + soff_), "l"(sa_), "r"(sz_));                     \
            const __half* sb_ = Bk_ + (size_t)(bn0 + row_) * K + ch_ * 8;     \
            asm volatile("cp.async.cg.shared.global [%0], [%1], 16;" ::       \
                "r"(bbase_ + soff_), "l"(sb_));                               \
        }                                                                     \
    }                                                                         \
    asm volatile("cp.async.commit_group;");                                   \
} while (0)

#define COMPUTE_TILE(ST) do {                                                 \
    const unsigned abase_ = smbase + (unsigned)(ST) * T_TSB;                  \
    const unsigned bbase_ = smbase + (unsigned)NSTG * T_TSB + (unsigned)(ST) * T_TSB; \
    _Pragma("unroll")                                                         \
    for (int kk_ = 0; kk_ < 4; kk_++) {                                       \
        const int chl_ = 2 * kk_ + (lane >> 4);                               \
        unsigned Ar[4][4];                                                    \
        unsigned Br[2][4];                                                    \
        _Pragma("unroll")                                                     \
        for (int mt_ = 0; mt_ < 4; mt_++) {                                   \
            const int r_ = wm + mt_ * 16 + (lane & 15);                       \
            LDSM_X4(Ar[mt_][0], Ar[mt_][1], Ar[mt_][2], Ar[mt_][3],           \
                    abase_ + (unsigned)(r_ * 128 + ((chl_ ^ (r_ & 7)) * 16)));\
        }                                                                     \
        _Pragma("unroll")                                                     \
        for (int np_ = 0; np_ < 2; np_++) {                                   \
            const int r_ = wn + np_ * 16 + (lane & 15);                       \
            LDSM_X4(Br[np_][0], Br[np_][1], Br[np_][2], Br[np_][3],           \
                    bbase_ + (unsigned)(r_ * 128 + ((chl_ ^ (r_ & 7)) * 16)));\
        }                                                                     \
        _Pragma("unroll")                                                     \
        for (int mt_ = 0; mt_ < 4; mt_++)                                     \
            _Pragma("unroll")                                                 \
            for (int np_ = 0; np_ < 2; np_++) {                               \
                MMA_F16(acc[mt_][np_ * 2 + 0], Ar[mt_][0], Ar[mt_][1],        \
                        Ar[mt_][2], Ar[mt_][3], Br[np_][0], Br[np_][2]);      \
                MMA_F16(acc[mt_][np_ * 2 + 1], Ar[mt_][0], Ar[mt_][1],        \
                        Ar[mt_][2], Ar[mt_][3], Br[np_][1], Br[np_][3]);      \
            }                                                                 \
    }                                                                         \
} while (0)

template<int ACT, int RES, int O32, int O16>
__global__ void __launch_bounds__(256, 2) gemm_h(
    const __half* __restrict__ A, int lda,
    const __half* __restrict__ Wt, int K,
    const float* __restrict__ bias,
    float* __restrict__ C32, __half* __restrict__ C16, int ldc,
    const float* __restrict__ res, int ldres,
    int M, int N)
{
    extern __shared__ __half smh[];
    const int tid  = threadIdx.x;
    const int bm0  = blockIdx.y * 128;
    const int bn0  = blockIdx.x * 128;
    const int lane = tid & 31, warp = tid >> 5;
    const int wm = (warp & 1) * 64;
    const int wn = (warp >> 1) * 32;
    const int gid = lane >> 2, tig = lane & 3;

    const unsigned smbase = (unsigned)__cvta_generic_to_shared(smh);

    float acc[4][4][4];
#pragma unroll
    for (int i = 0; i < 4; i++)
#pragma unroll
        for (int j = 0; j < 4; j++)
#pragma unroll
            for (int r = 0; r < 4; r++) acc[i][j][r] = 0.f;

    const int KT = K >> 6;

    LOAD_TILE(0, 0);
    LOAD_TILE(1, 1);

    for (int kt = 0; kt < KT; kt++) {
        asm volatile("cp.async.wait_group 1;");
        __syncthreads();
        LOAD_TILE(kt + 2, (kt + 2) % 3);
        COMPUTE_TILE(kt % 3);
    }

#pragma unroll
    for (int mt = 0; mt < 4; mt++) {
        const int mbase = bm0 + wm + mt * 16 + gid;
#pragma unroll
        for (int half_ = 0; half_ < 2; half_++) {
            const int m = mbase + half_ * 8;
            if (m >= M) continue;
#pragma unroll
            for (int nt = 0; nt < 4; nt++) {
                const int n = bn0 + wn + nt * 8 + tig * 2;
                const float2 bv = *(const float2*)(bias + n);
                float v0 = acc[mt][nt][half_ * 2 + 0] + bv.x;
                float v1 = acc[mt][nt][half_ * 2 + 1] + bv.y;
                if (RES == 1) {
                    const float2 r = *(const float2*)(res + (size_t)m * ldres + n);
                    v0 += r.x; v1 += r.y;
                }
                if (ACT == 1) {
                    v0 = v0 / (1.f + __expf(-v0));
                    v1 = v1 / (1.f + __expf(-v1));
                }
                if (O32)
                    *(float2*)(C32 + (size_t)m * ldc + n) = make_float2(v0, v1);
                if (O16)
                    *(__half2*)(C16 + (size_t)m * ldc + n) =
                        __float22half2_rn(make_float2(v0, v1));
            }
        }
    }
}

// ---------------- fused GEMM + LayerNorm --------------------------------------
// Y = LN( A @ W^T + bias + residual ) ; N = 256 (full row per CTA), M%64==0.
// BM=64, BN=256, BK=32, 256 threads (8 warps 2Mx4N, warp tile 32x64),
// 4-stage ring, 64B smem rows with ch^(row&3) swizzle.
#define LN_A_TSB 4096                /* 64 rows x 64 B */
#define LN_B_TSB 16384               /* 256 rows x 64 B */
#define LN_NSTG 4
#define LN_SMEM (LN_NSTG*(LN_A_TSB+LN_B_TSB))   /* 81920 -> 2 CTAs/SM */

#define LOAD_LN(CH, ST) do {                                                  \
    if ((CH) < KT) {                                                          \
        const unsigned abase_ = smbase + (unsigned)(ST) * LN_A_TSB;           \
        const unsigned bbase_ = smbase + (unsigned)LN_NSTG * LN_A_TSB         \
                                + (unsigned)(ST) * LN_B_TSB;                  \
        const __half* Ak_ = A + (size_t)(CH) * 32;                            \
        const __half* Bk_ = Wt + (size_t)(CH) * 32;                           \
        {                                                                     \
            const int row_ = tid >> 2, ch_ = tid & 3;                         \
            const __half* sa_ = Ak_ + (size_t)(bm0 + row_) * lda + ch_ * 8;   \
            asm volatile("cp.async.cg.shared.global [%0], [%1], 16;" ::       \
                "r"(abase_ + (unsigned)(row_ * 64 + ((ch_ ^ (row_ & 3)) * 16))), \
                "l"(sa_));                                                    \
        }                                                                     \
        _Pragma("unroll")                                                     \
        for (int i_ = 0; i_ < 4; i_++) {                                      \
            const int c_ = tid + 256 * i_;                                    \
            const int row_ = c_ >> 2, ch_ = c_ & 3;                           \
            const __half* sb_ = Bk_ + (size_t)row_ * K + ch_ * 8;             \
            asm volatile("cp.async.cg.shared.global [%0], [%1], 16;" ::       \
                "r"(bbase_ + (unsigned)(row_ * 64 + ((ch_ ^ (row_ & 3)) * 16))), \
                "l"(sb_));                                                    \
        }                                                                     \
    }                                                                         \
    asm volatile("cp.async.commit_group;");                                   \
} while (0)

#define COMPUTE_LN(ST) do {                                                   \
    const unsigned abase_ = smbase + (unsigned)(ST) * LN_A_TSB;               \
    const unsigned bbase_ = smbase + (unsigned)LN_NSTG * LN_A_TSB             \
                            + (unsigned)(ST) * LN_B_TSB;                      \
    _Pragma("unroll")                                                         \
    for (int kk_ = 0; kk_ < 2; kk_++) {                                       \
        const int chl_ = 2 * kk_ + (lane >> 4);                               \
        unsigned Ar[2][4];                                                    \
        unsigned Br[4][4];                                                    \
        _Pragma("unroll")                                                     \
        for (int mt_ = 0; mt_ < 2; mt_++) {                                   \
            const int r_ = wm + mt_ * 16 + (lane & 15);                       \
            LDSM_X4(Ar[mt_][0], Ar[mt_][1], Ar[mt_][2], Ar[mt_][3],           \
                    abase_ + (unsigned)(r_ * 64 + ((chl_ ^ (r_ & 3)) * 16))); \
        }                                                                     \
        _Pragma("unroll")                                                     \
        for (int np_ = 0; np_ < 4; np_++) {                                   \
            const int r_ = wn + np_ * 16 + (lane & 15);                       \
            LDSM_X4(Br[np_][0], Br[np_][1], Br[np_][2], Br[np_][3],           \
                    bbase_ + (unsigned)(r_ * 64 + ((chl_ ^ (r_ & 3)) * 16))); \
        }                                                                     \
        _Pragma("unroll")                                                     \
        for (int mt_ = 0; mt_ < 2; mt_++)                                     \
            _Pragma("unroll")                                                 \
            for (int np_ = 0; np_ < 4; np_++) {                               \
                MMA_F16(acc[mt_][np_ * 2 + 0], Ar[mt_][0], Ar[mt_][1],        \
                        Ar[mt_][2], Ar[mt_][3], Br[np_][0], Br[np_][2]);      \
                MMA_F16(acc[mt_][np_ * 2 + 1], Ar[mt_][0], Ar[mt_][1],        \
                        Ar[mt_][2], Ar[mt_][3], Br[np_][1], Br[np_][3]);      \
            }                                                                 \
    }                                                                         \
} while (0)

template<int RES>
__global__ void __launch_bounds__(256, 2) gemm_ln(
    const __half* __restrict__ A, int lda,
    const __half* __restrict__ Wt, int K,
    const float* __restrict__ bias,
    const float* __restrict__ lng, const float* __restrict__ lnb,
    float* __restrict__ Y32, __half* __restrict__ Y16,
    const float* __restrict__ res, int ldres, int M)
{
    extern __shared__ __half smh[];
    const int tid  = threadIdx.x;
    const int bm0  = blockIdx.x * 64;
    const int lane = tid & 31, warp = tid >> 5;
    const int wm = (warp & 1) * 32;
    const int wn = (warp >> 1) * 64;
    const int gid = lane >> 2, tig = lane & 3;
    const int ng = warp >> 1;
    (void)M;

    const unsigned smbase = (unsigned)__cvta_generic_to_shared(smh);

    float acc[2][8][4];
#pragma unroll
    for (int i = 0; i < 2; i++)
#pragma unroll
        for (int j = 0; j < 8; j++)
#pragma unroll
            for (int r = 0; r < 4; r++) acc[i][j][r] = 0.f;

    const int KT = K >> 5;

    LOAD_LN(0, 0);
    LOAD_LN(1, 1);
    LOAD_LN(2, 2);

    for (int kt = 0; kt < KT; kt++) {
        asm volatile("cp.async.wait_group 2;");
        __syncthreads();
        LOAD_LN(kt + 3, (kt + 3) & 3);
        COMPUTE_LN(kt & 3);
    }

    __syncthreads();   // smem ring free -> reuse for reductions

    // bias + residual into accumulators
#pragma unroll
    for (int mt = 0; mt < 2; mt++)
#pragma unroll
        for (int nt = 0; nt < 8; nt++) {
            const int n = wn + nt * 8 + tig * 2;
            const float2 bv = *(const float2*)(bias + n);
#pragma unroll
            for (int rh = 0; rh < 2; rh++) {
                const int m = bm0 + wm + mt * 16 + gid + rh * 8;
                float v0 = acc[mt][nt][rh * 2 + 0] + bv.x;
                float v1 = acc[mt][nt][rh * 2 + 1] + bv.y;
                if (RES == 1) {
                    const float2 r = *(const float2*)(res + (size_t)m * ldres + n);
                    v0 += r.x; v1 += r.y;
                }
                if (RES == 2) {
                    const int nw = m >> 6, w = m & 63;
                    const int b = nw >> 10, s = nw & 1023;
                    const float* rp = res + ((size_t)(b * PADS + s + w)) * ldres + n;
                    v0 += rp[0]; v1 += rp[1];
                }
                acc[mt][nt][rh * 2 + 0] = v0;
                acc[mt][nt][rh * 2 + 1] = v1;
            }
        }

    float* red = (float*)smh;
    float mean_[2][2], rstd_[2][2];

    // row sums -> mean
#pragma unroll
    for (int mt = 0; mt < 2; mt++)
#pragma unroll
        for (int rh = 0; rh < 2; rh++) {
            float s = 0.f;
#pragma unroll
            for (int nt = 0; nt < 8; nt++)
                s += acc[mt][nt][rh * 2] + acc[mt][nt][rh * 2 + 1];
            s += __shfl_xor_sync(0xffffffffu, s, 1);
            s += __shfl_xor_sync(0xffffffffu, s, 2);
            const int lr = wm + mt * 16 + gid + rh * 8;
            if (tig == 0) red[lr * 4 + ng] = s;
        }
    __syncthreads();
#pragma unroll
    for (int mt = 0; mt < 2; mt++)
#pragma unroll
        for (int rh = 0; rh < 2; rh++) {
            const int lr = wm + mt * 16 + gid + rh * 8;
            mean_[mt][rh] = (red[lr * 4] + red[lr * 4 + 1] +
                             red[lr * 4 + 2] + red[lr * 4 + 3]) * (1.f / 256.f);
        }

    // variance
#pragma unroll
    for (int mt = 0; mt < 2; mt++)
#pragma unroll
        for (int rh = 0; rh < 2; rh++) {
            float v = 0.f;
#pragma unroll
            for (int nt = 0; nt < 8; nt++) {
                float d0 = acc[mt][nt][rh * 2 + 0] - mean_[mt][rh];
                float d1 = acc[mt][nt][rh * 2 + 1] - mean_[mt][rh];
                v = fmaf(d0, d0, v);
                v = fmaf(d1, d1, v);
            }
            v += __shfl_xor_sync(0xffffffffu, v, 1);
            v += __shfl_xor_sync(0xffffffffu, v, 2);
            const int lr = wm + mt * 16 + gid + rh * 8;
            if (tig == 0) red[256 + lr * 4 + ng] = v;
        }
    __syncthreads();
#pragma unroll
    for (int mt = 0; mt < 2; mt++)
#pragma unroll
        for (int rh = 0; rh < 2; rh++) {
            const int lr = wm + mt * 16 + gid + rh * 8;
            float v = red[256 + lr * 4] + red[256 + lr * 4 + 1] +
                      red[256 + lr * 4 + 2] + red[256 + lr * 4 + 3];
            rstd_[mt][rh] = rsqrtf(v * (1.f / 256.f) + 1e-5f);
        }

    // normalize + affine + write
#pragma unroll
    for (int mt = 0; mt < 2; mt++)
#pragma unroll
        for (int nt = 0; nt < 8; nt++) {
            const int n = wn + nt * 8 + tig * 2;
            const float2 gg = *(const float2*)(lng + n);
            const float2 b2 = *(const float2*)(lnb + n);
#pragma unroll
            for (int rh = 0; rh < 2; rh++) {
                const int m = bm0 + wm + mt * 16 + gid + rh * 8;
                float y0 = (acc[mt][nt][rh * 2 + 0] - mean_[mt][rh]) * rstd_[mt][rh] * gg.x + b2.x;
                float y1 = (acc[mt][nt][rh * 2 + 1] - mean_[mt][rh]) * rstd_[mt][rh] * gg.y + b2.y;
                *(float2*)(Y32 + (size_t)m * 256 + n) = make_float2(y0, y1);
                *(__half2*)(Y16 + (size_t)m * 256 + n) =
                    __float22half2_rn(make_float2(y0, y1));
            }
        }
}

// ---------------- small fp32 GEMM (head only, N=10) --------------------------
__global__ void __launch_bounds__(256) gemm_head(
    const float* __restrict__ A, int lda,
    const float* __restrict__ Wt, int K,
    const float* __restrict__ bias,
    float* __restrict__ C, int ldc, int M, int N)
{
    __shared__ float As[16][68];
    __shared__ float Bs[16][68];
    const int tid = threadIdx.x;
    const int m0 = blockIdx.y * 64;
    const int lr = tid >> 2;
    const int lc = (tid & 3) << 2;
    const int ty = tid >> 4;
    const int tx = tid & 15;

    float acc[4][4];
#pragma unroll
    for (int i = 0; i < 4; i++)
#pragma unroll
        for (int j = 0; j < 4; j++) acc[i][j] = 0.f;

    const int am = m0 + lr;
    const float* Aptr = A + (size_t)am * lda + lc;
    const float* Wptr = Wt + (size_t)lr * K + lc;
    const bool avalid = (am < M);
    const bool bvalid = (lr < N);

    for (int k0 = 0; k0 < K; k0 += 16) {
        float4 av = make_float4(0.f, 0.f, 0.f, 0.f);
        float4 bv = make_float4(0.f, 0.f, 0.f, 0.f);
        if (avalid) av = *(const float4*)(Aptr + k0);
        if (bvalid) bv = *(const float4*)(Wptr + k0);
        As[lc+0][lr] = av.x; As[lc+1][lr] = av.y;
        As[lc+2][lr] = av.z; As[lc+3][lr] = av.w;
        Bs[lc+0][lr] = bv.x; Bs[lc+1][lr] = bv.y;
        Bs[lc+2][lr] = bv.z; Bs[lc+3][lr] = bv.w;
        __syncthreads();
#pragma unroll
        for (int kk = 0; kk < 16; kk++) {
            float4 a4 = *(const float4*)&As[kk][ty << 2];
            float4 b4 = *(const float4*)&Bs[kk][tx << 2];
            float ar[4] = {a4.x, a4.y, a4.z, a4.w};
            float br[4] = {b4.x, b4.y, b4.z, b4.w};
#pragma unroll
            for (int i = 0; i < 4; i++)
#pragma unroll
                for (int j = 0; j < 4; j++)
                    acc[i][j] = fmaf(ar[i], br[j], acc[i][j]);
        }
        __syncthreads();
    }

#pragma unroll
    for (int i = 0; i < 4; i++) {
        int m = m0 + (ty << 2) + i;
        if (m >= M) continue;
#pragma unroll
        for (int j = 0; j < 4; j++) {
            int n = (tx << 2) + j;
            if (n >= N) continue;
            C[(size_t)m * ldc + n] = acc[i][j] + bias[n];
        }
    }
}

// ---------------- tensor-core layer-0 attention (R12, unchanged) --------------
#define ATT_STR 776
#define ATT_SMEM (64*ATT_STR*2)

__global__ void __launch_bounds__(256) attn0_tc(const __half* __restrict__ qkv16,
                                                __half* __restrict__ octx16) {
    extern __shared__ __half sma[];
    const unsigned smb = (unsigned)__cvta_generic_to_shared(sma);
    const int n = blockIdx.x, b = n >> 10, s = n & 1023;
    const int tid = threadIdx.x, lane = tid & 31, h = tid >> 5;
    const int gid = lane >> 2, tig = lane & 3;
    const int lrow = lane & 15, lch = lane >> 4;

#pragma unroll
    for (int i = 0; i < 24; i++) {
        const int c = tid + 256 * i;
        const int row = c / 96, ch = c - row * 96;
        const __half* src = qkv16 + (size_t)(b * PADS + s + row) * 768 + ch * 8;
        asm volatile("cp.async.cg.shared.global [%0], [%1], 16;" ::
            "r"(smb + (unsigned)((row * ATT_STR + ch * 8) * 2)), "l"(src));
    }
    asm volatile("cp.async.commit_group;");
    asm volatile("cp.async.wait_group 0;");
    __syncthreads();

    float sacc[4][8][4];
#pragma unroll
    for (int i = 0; i < 4; i++)
#pragma unroll
        for (int j = 0; j < 8; j++)
#pragma unroll
            for (int r = 0; r < 4; r++) sacc[i][j][r] = 0.f;

#pragma unroll
    for (int kk = 0; kk < 2; kk++) {
        unsigned qa[4][4], kb[4][4];
        const int kcol = h * 32 + kk * 16 + lch * 8;
#pragma unroll
        for (int mt = 0; mt < 4; mt++)
            LDSM_X4(qa[mt][0], qa[mt][1], qa[mt][2], qa[mt][3],
                    smb + (unsigned)(((mt * 16 + lrow) * ATT_STR + kcol) * 2));
#pragma unroll
        for (int kt = 0; kt < 4; kt++)
            LDSM_X4(kb[kt][0], kb[kt][1], kb[kt][2], kb[kt][3],
                    smb + (unsigned)(((kt * 16 + lrow) * ATT_STR + 256 + kcol) * 2));
#pragma unroll
        for (int mt = 0; mt < 4; mt++)
#pragma unroll
            for (int kt = 0; kt < 4; kt++) {
                MMA_F16(sacc[mt][kt * 2 + 0], qa[mt][0], qa[mt][1], qa[mt][2], qa[mt][3],
                        kb[kt][0], kb[kt][2]);
                MMA_F16(sacc[mt][kt * 2 + 1], qa[mt][0], qa[mt][1], qa[mt][2], qa[mt][3],
                        kb[kt][1], kb[kt][3]);
            }
    }

#pragma unroll
    for (int mt = 0; mt < 4; mt++)
#pragma unroll
        for (int rh = 0; rh < 2; rh++) {
            float mx = -1e30f;
#pragma unroll
            for (int nt = 0; nt < 8; nt++)
                mx = fmaxf(mx, fmaxf(sacc[mt][nt][rh * 2], sacc[mt][nt][rh * 2 + 1]));
            mx = fmaxf(mx, __shfl_xor_sync(0xffffffffu, mx, 1));
            mx = fmaxf(mx, __shfl_xor_sync(0xffffffffu, mx, 2));
            float sum = 0.f;
#pragma unroll
            for (int nt = 0; nt < 8; nt++) {
                float e0 = __expf((sacc[mt][nt][rh * 2 + 0] - mx) * ATTN_SCALE);
                float e1 = __expf((sacc[mt][nt][rh * 2 + 1] - mx) * ATTN_SCALE);
                sacc[mt][nt][rh * 2 + 0] = e0;
                sacc[mt][nt][rh * 2 + 1] = e1;
                sum += e0 + e1;
            }
            sum += __shfl_xor_sync(0xffffffffu, sum, 1);
            sum += __shfl_xor_sync(0xffffffffu, sum, 2);
            const float inv = 1.f / sum;
#pragma unroll
            for (int nt = 0; nt < 8; nt++) {
                sacc[mt][nt][rh * 2 + 0] *= inv;
                sacc[mt][nt][rh * 2 + 1] *= inv;
            }
        }

    float oacc[4][4][4];
#pragma unroll
    for (int i = 0; i < 4; i++)
#pragma unroll
        for (int j = 0; j < 4; j++)
#pragma unroll
            for (int r = 0; r < 4; r++) oacc[i][j][r] = 0.f;

#pragma unroll
    for (int j = 0; j < 4; j++) {
        unsigned vb[2][4];
#pragma unroll
        for (int dc = 0; dc < 2; dc++)
            LDSM_X4T(vb[dc][0], vb[dc][1], vb[dc][2], vb[dc][3],
                     smb + (unsigned)(((j * 16 + lrow) * ATT_STR + 512 + h * 32
                                       + dc * 16 + lch * 8) * 2));
#pragma unroll
        for (int mt = 0; mt < 4; mt++) {
            __half2 h0 = __float22half2_rn(make_float2(sacc[mt][2*j][0],   sacc[mt][2*j][1]));
            __half2 h1 = __float22half2_rn(make_float2(sacc[mt][2*j][2],   sacc[mt][2*j][3]));
            __half2 h2 = __float22half2_rn(make_float2(sacc[mt][2*j+1][0], sacc[mt][2*j+1][1]));
            __half2 h3 = __float22half2_rn(make_float2(sacc[mt][2*j+1][2], sacc[mt][2*j+1][3]));
            const unsigned a0 = *(unsigned*)&h0, a1 = *(unsigned*)&h1;
            const unsigned a2 = *(unsigned*)&h2, a3 = *(unsigned*)&h3;
#pragma unroll
            for (int dc = 0; dc < 2; dc++) {
                MMA_F16(oacc[mt][dc * 2 + 0], a0, a1, a2, a3, vb[dc][0], vb[dc][1]);
                MMA_F16(oacc[mt][dc * 2 + 1], a0, a1, a2, a3, vb[dc][2], vb[dc][3]);
            }
        }
    }

#pragma unroll
    for (int mt = 0; mt < 4; mt++)
#pragma unroll
        for (int rh = 0; rh < 2; rh++) {
            const int q = mt * 16 + gid + rh * 8;
            __half* orow = octx16 + ((size_t)n * 64 + q) * E + h * 32;
#pragma unroll
            for (int on = 0; on < 4; on++) {
                __half2 o = __float22half2_rn(
                    make_float2(oacc[mt][on][rh * 2 + 0], oacc[mt][on][rh * 2 + 1]));
                *(__half2*)(orow + on * 8 + tig * 2) = o;
            }
        }
}

// ---------------- layer-1 attention ------------------------------------------
__global__ void __launch_bounds__(256) attn1_k(const __half* __restrict__ q1,
                                               const __half* __restrict__ kv1,
                                               __half* __restrict__ o1) {
    const int n = blockIdx.x;
    const int h = threadIdx.x >> 5, l = threadIdx.x & 31;
    __shared__ float qs[256];
    __shared__ float ps[8][64];
    qs[threadIdx.x] = __half2float(q1[(size_t)n * E + threadIdx.x]);
    __syncthreads();

    const __half* kvb = kv1 + (size_t)n * 64 * (2 * E);
    const float* qh  = &qs[h * 32];
    const __half2* k0p = (const __half2*)(kvb + (size_t)l * (2 * E) + h * 32);
    const __half2* k1p = (const __half2*)(kvb + (size_t)(l + 32) * (2 * E) + h * 32);
    float s0 = 0.f, s1 = 0.f;
#pragma unroll
    for (int d = 0; d < 16; d++) {
        const float2 a = __half22float2(k0p[d]);
        const float2 b = __half22float2(k1p[d]);
        s0 = fmaf(qh[2*d], a.x, s0); s0 = fmaf(qh[2*d+1], a.y, s0);
        s1 = fmaf(qh[2*d], b.x, s1); s1 = fmaf(qh[2*d+1], b.y, s1);
    }
    s0 *= ATTN_SCALE; s1 *= ATTN_SCALE;
    float m = fmaxf(s0, s1);
#pragma unroll
    for (int o = 16; o; o >>= 1) m = fmaxf(m, __shfl_xor_sync(0xffffffffu, m, o));
    float e0 = __expf(s0 - m), e1 = __expf(s1 - m);
    float sum = e0 + e1;
#pragma unroll
    for (int o = 16; o; o >>= 1) sum += __shfl_xor_sync(0xffffffffu, sum, o);
    const float inv = 1.f / sum;
    ps[h][l] = e0 * inv;
    ps[h][l + 32] = e1 * inv;
    __syncwarp();

    float acc = 0.f;
#pragma unroll 4
    for (int k = 0; k < 64; k++)
        acc = fmaf(ps[h][k], __half2float(kvb[(size_t)k * (2 * E) + E + h * 32 + l]), acc);
    o1[(size_t)n * E + h * 32 + l] = __float2half(acc);
}

// ---------------------------------------------------------------------------
extern "C" void kernel_launch(void* const* d_in, const int* in_sizes, int n_in,
                              void* d_out, int out_size) {
    (void)in_sizes; (void)n_in; (void)out_size;
    const float* inputs     = (const float*)d_in[0];
    const float* embed_w    = (const float*)d_in[1];
    const float* embed_b    = (const float*)d_in[2];
    const float* qkv_w      = (const float*)d_in[3];
    const float* qkv_b      = (const float*)d_in[4];
    const float* attn_out_w = (const float*)d_in[5];
    const float* attn_out_b = (const float*)d_in[6];
    const float* ln1_g      = (const float*)d_in[7];
    const float* ln1_b      = (const float*)d_in[8];
    const float* ffn1_w     = (const float*)d_in[9];
    const float* ffn1_b     = (const float*)d_in[10];
    const float* ffn2_w     = (const float*)d_in[11];
    const float* ffn2_b     = (const float*)d_in[12];
    const float* ln2_g      = (const float*)d_in[13];
    const float* ln2_b      = (const float*)d_in[14];
    const float* head_w     = (const float*)d_in[15];
    const float* head_b     = (const float*)d_in[16];
    float* out = (float*)d_out;

    float *emb32, *x1_32, *x2_32, *t1_32, *t2;
    __half *in16, *embw16, *qkvw16, *aow16, *f1w16, *f2w16;
    __half *emb16, *qkv16, *octx16, *x1_16, *h16, *x2_16, *kv16;
    __half *q1_16, *o1_16, *t1_16, *th16;
    cudaGetSymbolAddress((void**)&emb32, g_emb32);
    cudaGetSymbolAddress((void**)&x1_32, g_x1_32);
    cudaGetSymbolAddress((void**)&x2_32, g_x2_32);
    cudaGetSymbolAddress((void**)&t1_32, g_t1_32);
    cudaGetSymbolAddress((void**)&t2,    g_t2);
    cudaGetSymbolAddress((void**)&in16,  g_in16);
    cudaGetSymbolAddress((void**)&embw16,g_embw16);
    cudaGetSymbolAddress((void**)&qkvw16,g_qkvw16);
    cudaGetSymbolAddress((void**)&aow16, g_aow16);
    cudaGetSymbolAddress((void**)&f1w16, g_f1w16);
    cudaGetSymbolAddress((void**)&f2w16, g_f2w16);
    cudaGetSymbolAddress((void**)&emb16, g_emb16);
    cudaGetSymbolAddress((void**)&qkv16, g_qkv16);
    cudaGetSymbolAddress((void**)&octx16,g_octx16);
    cudaGetSymbolAddress((void**)&x1_16, g_x1_16);
    cudaGetSymbolAddress((void**)&h16,   g_h16);
    cudaGetSymbolAddress((void**)&x2_16, g_x2_16);
    cudaGetSymbolAddress((void**)&kv16,  g_kv16);
    cudaGetSymbolAddress((void**)&q1_16, g_q1_16);
    cudaGetSymbolAddress((void**)&o1_16, g_o1_16);
    cudaGetSymbolAddress((void**)&t1_16, g_t1_16);
    cudaGetSymbolAddress((void**)&th16,  g_th16);

    cudaFuncSetAttribute(gemm_h<0,0,1,1>, cudaFuncAttributeMaxDynamicSharedMemorySize, GEMM_SMEM);
    cudaFuncSetAttribute(gemm_h<0,0,0,1>, cudaFuncAttributeMaxDynamicSharedMemorySize, GEMM_SMEM);
    cudaFuncSetAttribute(gemm_h<1,0,0,1>, cudaFuncAttributeMaxDynamicSharedMemorySize, GEMM_SMEM);
    cudaFuncSetAttribute(gemm_ln<1>, cudaFuncAttributeMaxDynamicSharedMemorySize, LN_SMEM);
    cudaFuncSetAttribute(gemm_ln<2>, cudaFuncAttributeMaxDynamicSharedMemorySize, LN_SMEM);
    cudaFuncSetAttribute(attn0_tc, cudaFuncAttributeMaxDynamicSharedMemorySize, ATT_SMEM);

    // --- weight / input conversion ---
    conv_k<<<(BATCH*SEQ*FIN + 255)/256, 256>>>(inputs, in16, BATCH*SEQ*FIN);
    conv_k<<<(E*FIN + 255)/256, 256>>>(embed_w, embw16, E*FIN);
    conv_k<<<(2*3*E*E + 255)/256, 256>>>(qkv_w, qkvw16, 2*3*E*E);
    conv_k<<<(2*E*E + 255)/256, 256>>>(attn_out_w, aow16, 2*E*E);
    conv_k<<<(2*FF*E + 255)/256, 256>>>(ffn1_w, f1w16, 2*FF*E);
    conv_k<<<(2*E*FF + 255)/256, 256>>>(ffn2_w, f2w16, 2*E*FF);

    // --- embeddings (zero-padded left by W-1) ---
    zero_pad_k<<<63, 256>>>(emb32, emb16);
    for (int b = 0; b < BATCH; b++) {
        gemm_h<0,0,1,1><<<dim3(E/128, SEQ/128), 256, GEMM_SMEM>>>(
            in16 + (size_t)b * SEQ * FIN, FIN, embw16, FIN, embed_b,
            emb32 + ((size_t)b * PADS + (WCTX - 1)) * E,
            emb16 + ((size_t)b * PADS + (WCTX - 1)) * E, E,
            nullptr, 0, SEQ, E);
    }

    // --- layer-0 QKV per global token ---
    gemm_h<0,0,0,1><<<dim3(3*E/128, (BATCH*PADS + 127)/128), 256, GEMM_SMEM>>>(
        emb16, E, qkvw16, E, qkv_b, nullptr, qkv16, 3*E, nullptr, 0,
        BATCH*PADS, 3*E);

    // --- layer-0 attention (tensor cores) ---
    attn0_tc<<<NW, 256, ATT_SMEM>>>(qkv16, octx16);

    // --- layer-0 attn-out + residual(gather) + LN1 fused ---
    gemm_ln<2><<<NT/64, 256, LN_SMEM>>>(
        octx16, E, aow16, E, attn_out_b, ln1_g, ln1_b,
        x1_32, x1_16, emb32, E, NT);

    // --- layer-0 FFN ---
    gemm_h<1,0,0,1><<<dim3(FF/128, NT/128), 256, GEMM_SMEM>>>(
        x1_16, E, f1w16, E, ffn1_b, nullptr, h16, FF, nullptr, 0, NT, FF);
    gemm_ln<1><<<NT/64, 256, LN_SMEM>>>(
        h16, FF, f2w16, FF, ffn2_b, ln2_g, ln2_b,
        x2_32, x2_16, x1_32, E, NT);

    // --- layer-1: K,V all tokens; Q last tokens only ---
    gemm_h<0,0,0,1><<<dim3(2*E/128, NT/128), 256, GEMM_SMEM>>>(
        x2_16, E, qkvw16 + (size_t)3*E*E + (size_t)E*E, E,
        qkv_b + 3*E + E, nullptr, kv16, 2*E, nullptr, 0, NT, 2*E);
    gemm_h<0,0,0,1><<<dim3(E/128, NW/128), 256, GEMM_SMEM>>>(
        x2_16 + (size_t)(WCTX-1)*E, WCTX*E,
        qkvw16 + (size_t)3*E*E, E, qkv_b + 3*E,
        nullptr, q1_16, E, nullptr, 0, NW, E);

    attn1_k<<<NW, 256>>>(q1_16, kv16, o1_16);

    // --- layer-1 tail (fused LN) ---
    gemm_ln<1><<<NW/64, 256, LN_SMEM>>>(
        o1_16, E, aow16 + (size_t)E*E, E, attn_out_b + E, ln1_g + E, ln1_b + E,
        t1_32, t1_16, x2_32 + (size_t)(WCTX-1)*E, WCTX*E, NW);
    gemm_h<1,0,0,1><<<dim3(FF/128, NW/128), 256, GEMM_SMEM>>>(
        t1_16, E, f1w16 + (size_t)FF*E, E, ffn1_b + FF,
        nullptr, th16, FF, nullptr, 0, NW, FF);
    gemm_ln<1><<<NW/64, 256, LN_SMEM>>>(
        th16, FF, f2w16 + (size_t)E*FF, FF, ffn2_b + E, ln2_g + E, ln2_b + E,
        t2, o1_16 /*scratch*/, t1_32, E, NW);

    // --- head (N=10, fp32) ---
    gemm_head<<<dim3(1, NW/64), 256>>>(
        t2, E, head_w, E, head_b, out, 10, NW, 10);
}

// round 14
// speedup vs baseline: 1.0065x; 1.0065x over previous
#include <cuda_runtime.h>
#include <cuda_fp16.h>
#include <math.h>
#include <stdint.h>

// ---------------------------------------------------------------------------
// Round 14: R12 structure for big-NT GEMMs (gemm_h + ln_k; undoes R13's
// barrier-heavy gemm_ln there), gemm_ln fusion kept ONLY for the tiny
// layer-1 tail (latency-bound, 32-CTA grids). 6 convs -> 1 launch, 2 emb
// GEMMs -> 1 batched launch. 24 -> 17 launches; attn-out gemm_h is launch #6
// so ncu finally profiles a real GEMM.
// ---------------------------------------------------------------------------

#define BATCH 2
#define SEQ   1024
#define E     256
#define FIN   64
#define FF    1024
#define WCTX  64
#define NW    (BATCH*SEQ)
#define PADS  (SEQ + WCTX - 1)
#define NT    (NW*WCTX)

#define ATTN_SCALE 0.17677669529663687f

// ---------------- scratch ----------------------------------------------------
__device__ __align__(128) float g_emb32[BATCH*PADS*E];
__device__ __align__(128) float g_x1a  [NT*E];
__device__ __align__(128) float g_x1_32[NT*E];
__device__ __align__(128) float g_x2_32[NT*E];
__device__ __align__(128) float g_t1_32[NW*E];
__device__ __align__(128) float g_t2   [NW*E];
__device__ __align__(128) __half g_in16  [BATCH*SEQ*FIN];
__device__ __align__(128) __half g_embw16[E*FIN];
__device__ __align__(128) __half g_qkvw16[2*3*E*E];
__device__ __align__(128) __half g_aow16 [2*E*E];
__device__ __align__(128) __half g_f1w16 [2*FF*E];
__device__ __align__(128) __half g_f2w16 [2*E*FF];
__device__ __align__(128) __half g_emb16 [BATCH*PADS*E];
__device__ __align__(128) __half g_qkv16 [BATCH*PADS*3*E];
__device__ __align__(128) __half g_octx16[NT*E];
__device__ __align__(128) __half g_x1_16 [NT*E];
__device__ __align__(128) __half g_h16   [NT*FF];
__device__ __align__(128) __half g_x2_16 [NT*E];
__device__ __align__(128) __half g_kv16  [NT*2*E];
__device__ __align__(128) __half g_q1_16 [NW*E];
__device__ __align__(128) __half g_o1_16 [NW*E];
__device__ __align__(128) __half g_t1_16 [NW*E];
__device__ __align__(128) __half g_th16  [NW*FF];

// ---------------- fused fp32->fp16 conversion (one launch) --------------------
struct ConvJobs {
    const float* s[6];
    __half* d[6];
    int n[6];
};
__global__ void conv_all(ConvJobs j) {
    int idx = blockIdx.x * 256 + threadIdx.x;
#pragma unroll
    for (int k = 0; k < 6; k++) {
        if (idx < j.n[k]) { j.d[k][idx] = __float2half(j.s[k][idx]); return; }
        idx -= j.n[k];
    }
}

__global__ void zero_pad_k(float* emb32, __half* emb16) {
    int i = blockIdx.x * 256 + threadIdx.x;
    if (i < (WCTX - 1) * E) {
        emb32[i] = 0.f;                 emb16[i] = __float2half(0.f);
        emb32[(size_t)PADS * E + i] = 0.f;
        emb16[(size_t)PADS * E + i] = __float2half(0.f);
    }
}

// ---------------- shared MMA / ldmatrix macros --------------------------------
#define MMA_F16(d, a0, a1, a2, a3, b0, b1) \
  asm volatile("mma.sync.aligned.m16n8k16.row.col.f32.f16.f16.f32 " \
    "{%0,%1,%2,%3}, {%4,%5,%6,%7}, {%8,%9}, {%0,%1,%2,%3};" \
    : "+f"(d[0]), "+f"(d[1]), "+f"(d[2]), "+f"(d[3]) \
    : "r"(a0), "r"(a1), "r"(a2), "r"(a3), "r"(b0), "r"(b1))

#define LDSM_X4(r0, r1, r2, r3, ad) \
  asm volatile("ldmatrix.sync.aligned.m8n8.x4.shared.b16 {%0,%1,%2,%3}, [%4];" \
    : "=r"(r0), "=r"(r1), "=r"(r2), "=r"(r3) : "r"(ad))

#define LDSM_X4T(r0, r1, r2, r3, ad) \
  asm volatile("ldmatrix.sync.aligned.m8n8.x4.trans.shared.b16 {%0,%1,%2,%3}, [%4];" \
    : "=r"(r0), "=r"(r1), "=r"(r2), "=r"(r3) : "r"(ad))

// ---------------- fp16 tensor-core GEMM (R11/R12 + batch-z) -------------------
#define T_TSB 16384
#define NSTG 3
#define GEMM_SMEM (2*NSTG*T_TSB)

#define LOAD_TILE(KT_IDX, ST) do {                                            \
    if ((KT_IDX) < KT) {                                                      \
        const unsigned abase_ = smbase + (unsigned)(ST) * T_TSB;              \
        const unsigned bbase_ = smbase + (unsigned)NSTG * T_TSB + (unsigned)(ST) * T_TSB; \
        const __half* Ak_ = A + (size_t)(KT_IDX) * 64;                        \
        const __half* Bk_ = Wt + (size_t)(KT_IDX) * 64;                       \
        _Pragma("unroll")                                                     \
        for (int i_ = 0; i_ < 4; i_++) {                                      \
            const int c_   = tid + 256 * i_;                                  \
            const int row_ = c_ >> 3;                                         \
            const int ch_  = c_ & 7;                                          \
            const unsigned soff_ = (unsigned)(row_ * 128 + ((ch_ ^ (row_ & 7)) * 16)); \
            const int am_  = bm0 + row_;                                      \
            const __half* sa_ = Ak_ + (size_t)(am_ < M ? am_ : 0) * lda + ch_ * 8; \
            const int sz_     = (am_ < M) ? 16 : 0;                           \
            asm volatile("cp.async.cg.shared.global [%0], [%1], 16, %2;" ::   \
                "r"(abase_ + soff_), "l"(sa_), "r"(sz_));                     \
            const __half* sb_ = Bk_ + (size_t)(bn0 + row_) * K + ch_ * 8;     \
            asm volatile("cp.async.cg.shared.global [%0], [%1], 16;" ::       \
                "r"(bbase_ + soff_), "l"(sb_));                               \
        }                                                                     \
    }                                                                         \
    asm volatile("cp.async.commit_group;");                                   \
} while (0)

#define COMPUTE_TILE(ST) do {                                                 \
    const unsigned abase_ = smbase + (unsigned)(ST) * T_TSB;                  \
    const unsigned bbase_ = smbase + (unsigned)NSTG * T_TSB + (unsigned)(ST) * T_TSB; \
    _Pragma("unroll")                                                         \
    for (int kk_ = 0; kk_ < 4; kk_++) {                                       \
        const int chl_ = 2 * kk_ + (lane >> 4);                               \
        unsigned Ar[4][4];                                                    \
        unsigned Br[2][4];                                                    \
        _Pragma("unroll")                                                     \
        for (int mt_ = 0; mt_ < 4; mt_++) {                                   \
            const int r_ = wm + mt_ * 16 + (lane & 15);                       \
            LDSM_X4(Ar[mt_][0], Ar[mt_][1], Ar[mt_][2], Ar[mt_][3],           \
                    abase_ + (unsigned)(r_ * 128 + ((chl_ ^ (r_ & 7)) * 16)));\
        }                                                                     \
        _Pragma("unroll")                                                     \
        for (int np_ = 0; np_ < 2; np_++) {                                   \
            const int r_ = wn + np_ * 16 + (lane & 15);                       \
            LDSM_X4(Br[np_][0], Br[np_][1], Br[np_][2], Br[np_][3],           \
                    bbase_ + (unsigned)(r_ * 128 + ((chl_ ^ (r_ & 7)) * 16)));\
        }                                                                     \
        _Pragma("unroll")                                                     \
        for (int mt_ = 0; mt_ < 4; mt_++)                                     \
            _Pragma("unroll")                                                 \
            for (int np_ = 0; np_ < 2; np_++) {                               \
                MMA_F16(acc[mt_][np_ * 2 + 0], Ar[mt_][0], Ar[mt_][1],        \
                        Ar[mt_][2], Ar[mt_][3], Br[np_][0], Br[np_][2]);      \
                MMA_F16(acc[mt_][np_ * 2 + 1], Ar[mt_][0], Ar[mt_][1],        \
                        Ar[mt_][2], Ar[mt_][3], Br[np_][1], Br[np_][3]);      \
            }                                                                 \
    }                                                                         \
} while (0)

template<int ACT, int RES, int O32, int O16>
__global__ void __launch_bounds__(256, 2) gemm_h(
    const __half* __restrict__ A, int lda,
    const __half* __restrict__ Wt, int K,
    const float* __restrict__ bias,
    float* __restrict__ C32, __half* __restrict__ C16, int ldc,
    const float* __restrict__ res, int ldres,
    int M, int N, int zA, int zC)
{
    extern __shared__ __half smh[];
    const int tid  = threadIdx.x;
    const int bm0  = blockIdx.y * 128;
    const int bn0  = blockIdx.x * 128;
    const int lane = tid & 31, warp = tid >> 5;
    const int wm = (warp & 1) * 64;
    const int wn = (warp >> 1) * 32;
    const int gid = lane >> 2, tig = lane & 3;

    A += (size_t)blockIdx.z * (size_t)zA;
    const size_t coff = (size_t)blockIdx.z * (size_t)zC;
    if (O32) C32 += coff;
    if (O16) C16 += coff;

    const unsigned smbase = (unsigned)__cvta_generic_to_shared(smh);

    float acc[4][4][4];
#pragma unroll
    for (int i = 0; i < 4; i++)
#pragma unroll
        for (int j = 0; j < 4; j++)
#pragma unroll
            for (int r = 0; r < 4; r++) acc[i][j][r] = 0.f;

    const int KT = K >> 6;

    LOAD_TILE(0, 0);
    LOAD_TILE(1, 1);

    for (int kt = 0; kt < KT; kt++) {
        asm volatile("cp.async.wait_group 1;");
        __syncthreads();
        LOAD_TILE(kt + 2, (kt + 2) % 3);
        COMPUTE_TILE(kt % 3);
    }

#pragma unroll
    for (int mt = 0; mt < 4; mt++) {
        const int mbase = bm0 + wm + mt * 16 + gid;
#pragma unroll
        for (int half_ = 0; half_ < 2; half_++) {
            const int m = mbase + half_ * 8;
            if (m >= M) continue;
#pragma unroll
            for (int nt = 0; nt < 4; nt++) {
                const int n = bn0 + wn + nt * 8 + tig * 2;
                const float2 bv = *(const float2*)(bias + n);
                float v0 = acc[mt][nt][half_ * 2 + 0] + bv.x;
                float v1 = acc[mt][nt][half_ * 2 + 1] + bv.y;
                if (RES == 1) {
                    const float2 r = *(const float2*)(res + (size_t)m * ldres + n);
                    v0 += r.x; v1 += r.y;
                }
                if (RES == 2) {
                    const int nw = m >> 6, w = m & 63;
                    const int b = nw >> 10, s = nw & 1023;
                    const float* rp = res + ((size_t)(b * PADS + s + w)) * ldres + n;
                    v0 += rp[0]; v1 += rp[1];
                }
                if (ACT == 1) {
                    v0 = v0 / (1.f + __expf(-v0));
                    v1 = v1 / (1.f + __expf(-v1));
                }
                if (O32)
                    *(float2*)(C32 + (size_t)m * ldc + n) = make_float2(v0, v1);
                if (O16)
                    *(__half2*)(C16 + (size_t)m * ldc + n) =
                        __float22half2_rn(make_float2(v0, v1));
            }
        }
    }
}

// ---------------- fused GEMM + LayerNorm (tail only; R13) ---------------------
#define LN_A_TSB 4096
#define LN_B_TSB 16384
#define LN_NSTG 4
#define LN_SMEM (LN_NSTG*(LN_A_TSB+LN_B_TSB))

#define LOAD_LN(CH, ST) do {                                                  \
    if ((CH) < KT) {                                                          \
        const unsigned abase_ = smbase + (unsigned)(ST) * LN_A_TSB;           \
        const unsigned bbase_ = smbase + (unsigned)LN_NSTG * LN_A_TSB         \
                                + (unsigned)(ST) * LN_B_TSB;                  \
        const __half* Ak_ = A + (size_t)(CH) * 32;                            \
        const __half* Bk_ = Wt + (size_t)(CH) * 32;                           \
        {                                                                     \
            const int row_ = tid >> 2, ch_ = tid & 3;                         \
            const __half* sa_ = Ak_ + (size_t)(bm0 + row_) * lda + ch_ * 8;   \
            asm volatile("cp.async.cg.shared.global [%0], [%1], 16;" ::       \
                "r"(abase_ + (unsigned)(row_ * 64 + ((ch_ ^ (row_ & 3)) * 16))), \
                "l"(sa_));                                                    \
        }                                                                     \
        _Pragma("unroll")                                                     \
        for (int i_ = 0; i_ < 4; i_++) {                                      \
            const int c_ = tid + 256 * i_;                                    \
            const int row_ = c_ >> 2, ch_ = c_ & 3;                           \
            const __half* sb_ = Bk_ + (size_t)row_ * K + ch_ * 8;             \
            asm volatile("cp.async.cg.shared.global [%0], [%1], 16;" ::       \
                "r"(bbase_ + (unsigned)(row_ * 64 + ((ch_ ^ (row_ & 3)) * 16))), \
                "l"(sb_));                                                    \
        }                                                                     \
    }                                                                         \
    asm volatile("cp.async.commit_group;");                                   \
} while (0)

#define COMPUTE_LN(ST) do {                                                   \
    const unsigned abase_ = smbase + (unsigned)(ST) * LN_A_TSB;               \
    const unsigned bbase_ = smbase + (unsigned)LN_NSTG * LN_A_TSB             \
                            + (unsigned)(ST) * LN_B_TSB;                      \
    _Pragma("unroll")                                                         \
    for (int kk_ = 0; kk_ < 2; kk_++) {                                       \
        const int chl_ = 2 * kk_ + (lane >> 4);                               \
        unsigned Ar[2][4];                                                    \
        unsigned Br[4][4];                                                    \
        _Pragma("unroll")                                                     \
        for (int mt_ = 0; mt_ < 2; mt_++) {                                   \
            const int r_ = wm + mt_ * 16 + (lane & 15);                       \
            LDSM_X4(Ar[mt_][0], Ar[mt_][1], Ar[mt_][2], Ar[mt_][3],           \
                    abase_ + (unsigned)(r_ * 64 + ((chl_ ^ (r_ & 3)) * 16))); \
        }                                                                     \
        _Pragma("unroll")                                                     \
        for (int np_ = 0; np_ < 4; np_++) {                                   \
            const int r_ = wn + np_ * 16 + (lane & 15);                       \
            LDSM_X4(Br[np_][0], Br[np_][1], Br[np_][2], Br[np_][3],           \
                    bbase_ + (unsigned)(r_ * 64 + ((chl_ ^ (r_ & 3)) * 16))); \
        }                                                                     \
        _Pragma("unroll")                                                     \
        for (int mt_ = 0; mt_ < 2; mt_++)                                     \
            _Pragma("unroll")                                                 \
            for (int np_ = 0; np_ < 4; np_++) {                               \
                MMA_F16(acc[mt_][np_ * 2 + 0], Ar[mt_][0], Ar[mt_][1],        \
                        Ar[mt_][2], Ar[mt_][3], Br[np_][0], Br[np_][2]);      \
                MMA_F16(acc[mt_][np_ * 2 + 1], Ar[mt_][0], Ar[mt_][1],        \
                        Ar[mt_][2], Ar[mt_][3], Br[np_][1], Br[np_][3]);      \
            }                                                                 \
    }                                                                         \
} while (0)

template<int RES>
__global__ void __launch_bounds__(256, 2) gemm_ln(
    const __half* __restrict__ A, int lda,
    const __half* __restrict__ Wt, int K,
    const float* __restrict__ bias,
    const float* __restrict__ lng, const float* __restrict__ lnb,
    float* __restrict__ Y32, __half* __restrict__ Y16,
    const float* __restrict__ res, int ldres, int M)
{
    extern __shared__ __half smh[];
    const int tid  = threadIdx.x;
    const int bm0  = blockIdx.x * 64;
    const int lane = tid & 31, warp = tid >> 5;
    const int wm = (warp & 1) * 32;
    const int wn = (warp >> 1) * 64;
    const int gid = lane >> 2, tig = lane & 3;
    const int ng = warp >> 1;
    (void)M;

    const unsigned smbase = (unsigned)__cvta_generic_to_shared(smh);

    float acc[2][8][4];
#pragma unroll
    for (int i = 0; i < 2; i++)
#pragma unroll
        for (int j = 0; j < 8; j++)
#pragma unroll
            for (int r = 0; r < 4; r++) acc[i][j][r] = 0.f;

    const int KT = K >> 5;

    LOAD_LN(0, 0);
    LOAD_LN(1, 1);
    LOAD_LN(2, 2);

    for (int kt = 0; kt < KT; kt++) {
        asm volatile("cp.async.wait_group 2;");
        __syncthreads();
        LOAD_LN(kt + 3, (kt + 3) & 3);
        COMPUTE_LN(kt & 3);
    }

    __syncthreads();

#pragma unroll
    for (int mt = 0; mt < 2; mt++)
#pragma unroll
        for (int nt = 0; nt < 8; nt++) {
            const int n = wn + nt * 8 + tig * 2;
            const float2 bv = *(const float2*)(bias + n);
#pragma unroll
            for (int rh = 0; rh < 2; rh++) {
                const int m = bm0 + wm + mt * 16 + gid + rh * 8;
                float v0 = acc[mt][nt][rh * 2 + 0] + bv.x;
                float v1 = acc[mt][nt][rh * 2 + 1] + bv.y;
                if (RES == 1) {
                    const float2 r = *(const float2*)(res + (size_t)m * ldres + n);
                    v0 += r.x; v1 += r.y;
                }
                acc[mt][nt][rh * 2 + 0] = v0;
                acc[mt][nt][rh * 2 + 1] = v1;
            }
        }

    float* red = (float*)smh;
    float mean_[2][2], rstd_[2][2];

#pragma unroll
    for (int mt = 0; mt < 2; mt++)
#pragma unroll
        for (int rh = 0; rh < 2; rh++) {
            float s = 0.f;
#pragma unroll
            for (int nt = 0; nt < 8; nt++)
                s += acc[mt][nt][rh * 2] + acc[mt][nt][rh * 2 + 1];
            s += __shfl_xor_sync(0xffffffffu, s, 1);
            s += __shfl_xor_sync(0xffffffffu, s, 2);
            const int lr = wm + mt * 16 + gid + rh * 8;
            if (tig == 0) red[lr * 4 + ng] = s;
        }
    __syncthreads();
#pragma unroll
    for (int mt = 0; mt < 2; mt++)
#pragma unroll
        for (int rh = 0; rh < 2; rh++) {
            const int lr = wm + mt * 16 + gid + rh * 8;
            mean_[mt][rh] = (red[lr * 4] + red[lr * 4 + 1] +
                             red[lr * 4 + 2] + red[lr * 4 + 3]) * (1.f / 256.f);
        }

#pragma unroll
    for (int mt = 0; mt < 2; mt++)
#pragma unroll
        for (int rh = 0; rh < 2; rh++) {
            float v = 0.f;
#pragma unroll
            for (int nt = 0; nt < 8; nt++) {
                float d0 = acc[mt][nt][rh * 2 + 0] - mean_[mt][rh];
                float d1 = acc[mt][nt][rh * 2 + 1] - mean_[mt][rh];
                v = fmaf(d0, d0, v);
                v = fmaf(d1, d1, v);
            }
            v += __shfl_xor_sync(0xffffffffu, v, 1);
            v += __shfl_xor_sync(0xffffffffu, v, 2);
            const int lr = wm + mt * 16 + gid + rh * 8;
            if (tig == 0) red[256 + lr * 4 + ng] = v;
        }
    __syncthreads();
#pragma unroll
    for (int mt = 0; mt < 2; mt++)
#pragma unroll
        for (int rh = 0; rh < 2; rh++) {
            const int lr = wm + mt * 16 + gid + rh * 8;
            float v = red[256 + lr * 4] + red[256 + lr * 4 + 1] +
                      red[256 + lr * 4 + 2] + red[256 + lr * 4 + 3];
            rstd_[mt][rh] = rsqrtf(v * (1.f / 256.f) + 1e-5f);
        }

#pragma unroll
    for (int mt = 0; mt < 2; mt++)
#pragma unroll
        for (int nt = 0; nt < 8; nt++) {
            const int n = wn + nt * 8 + tig * 2;
            const float2 gg = *(const float2*)(lng + n);
            const float2 b2 = *(const float2*)(lnb + n);
#pragma unroll
            for (int rh = 0; rh < 2; rh++) {
                const int m = bm0 + wm + mt * 16 + gid + rh * 8;
                float y0 = (acc[mt][nt][rh * 2 + 0] - mean_[mt][rh]) * rstd_[mt][rh] * gg.x + b2.x;
                float y1 = (acc[mt][nt][rh * 2 + 1] - mean_[mt][rh]) * rstd_[mt][rh] * gg.y + b2.y;
                *(float2*)(Y32 + (size_t)m * 256 + n) = make_float2(y0, y1);
                *(__half2*)(Y16 + (size_t)m * 256 + n) =
                    __float22half2_rn(make_float2(y0, y1));
            }
        }
}

// ---------------- small fp32 GEMM (head only, N=10) --------------------------
__global__ void __launch_bounds__(256) gemm_head(
    const float* __restrict__ A, int lda,
    const float* __restrict__ Wt, int K,
    const float* __restrict__ bias,
    float* __restrict__ C, int ldc, int M, int N)
{
    __shared__ float As[16][68];
    __shared__ float Bs[16][68];
    const int tid = threadIdx.x;
    const int m0 = blockIdx.y * 64;
    const int lr = tid >> 2;
    const int lc = (tid & 3) << 2;
    const int ty = tid >> 4;
    const int tx = tid & 15;

    float acc[4][4];
#pragma unroll
    for (int i = 0; i < 4; i++)
#pragma unroll
        for (int j = 0; j < 4; j++) acc[i][j] = 0.f;

    const int am = m0 + lr;
    const float* Aptr = A + (size_t)am * lda + lc;
    const float* Wptr = Wt + (size_t)lr * K + lc;
    const bool avalid = (am < M);
    const bool bvalid = (lr < N);

    for (int k0 = 0; k0 < K; k0 += 16) {
        float4 av = make_float4(0.f, 0.f, 0.f, 0.f);
        float4 bv = make_float4(0.f, 0.f, 0.f, 0.f);
        if (avalid) av = *(const float4*)(Aptr + k0);
        if (bvalid) bv = *(const float4*)(Wptr + k0);
        As[lc+0][lr] = av.x; As[lc+1][lr] = av.y;
        As[lc+2][lr] = av.z; As[lc+3][lr] = av.w;
        Bs[lc+0][lr] = bv.x; Bs[lc+1][lr] = bv.y;
        Bs[lc+2][lr] = bv.z; Bs[lc+3][lr] = bv.w;
        __syncthreads();
#pragma unroll
        for (int kk = 0; kk < 16; kk++) {
            float4 a4 = *(const float4*)&As[kk][ty << 2];
            float4 b4 = *(const float4*)&Bs[kk][tx << 2];
            float ar[4] = {a4.x, a4.y, a4.z, a4.w};
            float br[4] = {b4.x, b4.y, b4.z, b4.w};
#pragma unroll
            for (int i = 0; i < 4; i++)
#pragma unroll
                for (int j = 0; j < 4; j++)
                    acc[i][j] = fmaf(ar[i], br[j], acc[i][j]);
        }
        __syncthreads();
    }

#pragma unroll
    for (int i = 0; i < 4; i++) {
        int m = m0 + (ty << 2) + i;
        if (m >= M) continue;
#pragma unroll
        for (int j = 0; j < 4; j++) {
            int n = (tx << 2) + j;
            if (n >= N) continue;
            C[(size_t)m * ldc + n] = acc[i][j] + bias[n];
        }
    }
}

// ---------------- tensor-core layer-0 attention (R12, unchanged) --------------
#define ATT_STR 776
#define ATT_SMEM (64*ATT_STR*2)

__global__ void __launch_bounds__(256) attn0_tc(const __half* __restrict__ qkv16,
                                                __half* __restrict__ octx16) {
    extern __shared__ __half sma[];
    const unsigned smb = (unsigned)__cvta_generic_to_shared(sma);
    const int n = blockIdx.x, b = n >> 10, s = n & 1023;
    const int tid = threadIdx.x, lane = tid & 31, h = tid >> 5;
    const int gid = lane >> 2, tig = lane & 3;
    const int lrow = lane & 15, lch = lane >> 4;

#pragma unroll
    for (int i = 0; i < 24; i++) {
        const int c = tid + 256 * i;
        const int row = c / 96, ch = c - row * 96;
        const __half* src = qkv16 + (size_t)(b * PADS + s + row) * 768 + ch * 8;
        asm volatile("cp.async.cg.shared.global [%0], [%1], 16;" ::
            "r"(smb + (unsigned)((row * ATT_STR + ch * 8) * 2)), "l"(src));
    }
    asm volatile("cp.async.commit_group;");
    asm volatile("cp.async.wait_group 0;");
    __syncthreads();

    float sacc[4][8][4];
#pragma unroll
    for (int i = 0; i < 4; i++)
#pragma unroll
        for (int j = 0; j < 8; j++)
#pragma unroll
            for (int r = 0; r < 4; r++) sacc[i][j][r] = 0.f;

#pragma unroll
    for (int kk = 0; kk < 2; kk++) {
        unsigned qa[4][4], kb[4][4];
        const int kcol = h * 32 + kk * 16 + lch * 8;
#pragma unroll
        for (int mt = 0; mt < 4; mt++)
            LDSM_X4(qa[mt][0], qa[mt][1], qa[mt][2], qa[mt][3],
                    smb + (unsigned)(((mt * 16 + lrow) * ATT_STR + kcol) * 2));
#pragma unroll
        for (int kt = 0; kt < 4; kt++)
            LDSM_X4(kb[kt][0], kb[kt][1], kb[kt][2], kb[kt][3],
                    smb + (unsigned)(((kt * 16 + lrow) * ATT_STR + 256 + kcol) * 2));
#pragma unroll
        for (int mt = 0; mt < 4; mt++)
#pragma unroll
            for (int kt = 0; kt < 4; kt++) {
                MMA_F16(sacc[mt][kt * 2 + 0], qa[mt][0], qa[mt][1], qa[mt][2], qa[mt][3],
                        kb[kt][0], kb[kt][2]);
                MMA_F16(sacc[mt][kt * 2 + 1], qa[mt][0], qa[mt][1], qa[mt][2], qa[mt][3],
                        kb[kt][1], kb[kt][3]);
            }
    }

#pragma unroll
    for (int mt = 0; mt < 4; mt++)
#pragma unroll
        for (int rh = 0; rh < 2; rh++) {
            float mx = -1e30f;
#pragma unroll
            for (int nt = 0; nt < 8; nt++)
                mx = fmaxf(mx, fmaxf(sacc[mt][nt][rh * 2], sacc[mt][nt][rh * 2 + 1]));
            mx = fmaxf(mx, __shfl_xor_sync(0xffffffffu, mx, 1));
            mx = fmaxf(mx, __shfl_xor_sync(0xffffffffu, mx, 2));
            float sum = 0.f;
#pragma unroll
            for (int nt = 0; nt < 8; nt++) {
                float e0 = __expf((sacc[mt][nt][rh * 2 + 0] - mx) * ATTN_SCALE);
                float e1 = __expf((sacc[mt][nt][rh * 2 + 1] - mx) * ATTN_SCALE);
                sacc[mt][nt][rh * 2 + 0] = e0;
                sacc[mt][nt][rh * 2 + 1] = e1;
                sum += e0 + e1;
            }
            sum += __shfl_xor_sync(0xffffffffu, sum, 1);
            sum += __shfl_xor_sync(0xffffffffu, sum, 2);
            const float inv = 1.f / sum;
#pragma unroll
            for (int nt = 0; nt < 8; nt++) {
                sacc[mt][nt][rh * 2 + 0] *= inv;
                sacc[mt][nt][rh * 2 + 1] *= inv;
            }
        }

    float oacc[4][4][4];
#pragma unroll
    for (int i = 0; i < 4; i++)
#pragma unroll
        for (int j = 0; j < 4; j++)
#pragma unroll
            for (int r = 0; r < 4; r++) oacc[i][j][r] = 0.f;

#pragma unroll
    for (int j = 0; j < 4; j++) {
        unsigned vb[2][4];
#pragma unroll
        for (int dc = 0; dc < 2; dc++)
            LDSM_X4T(vb[dc][0], vb[dc][1], vb[dc][2], vb[dc][3],
                     smb + (unsigned)(((j * 16 + lrow) * ATT_STR + 512 + h * 32
                                       + dc * 16 + lch * 8) * 2));
#pragma unroll
        for (int mt = 0; mt < 4; mt++) {
            __half2 h0 = __float22half2_rn(make_float2(sacc[mt][2*j][0],   sacc[mt][2*j][1]));
            __half2 h1 = __float22half2_rn(make_float2(sacc[mt][2*j][2],   sacc[mt][2*j][3]));
            __half2 h2 = __float22half2_rn(make_float2(sacc[mt][2*j+1][0], sacc[mt][2*j+1][1]));
            __half2 h3 = __float22half2_rn(make_float2(sacc[mt][2*j+1][2], sacc[mt][2*j+1][3]));
            const unsigned a0 = *(unsigned*)&h0, a1 = *(unsigned*)&h1;
            const unsigned a2 = *(unsigned*)&h2, a3 = *(unsigned*)&h3;
#pragma unroll
            for (int dc = 0; dc < 2; dc++) {
                MMA_F16(oacc[mt][dc * 2 + 0], a0, a1, a2, a3, vb[dc][0], vb[dc][1]);
                MMA_F16(oacc[mt][dc * 2 + 1], a0, a1, a2, a3, vb[dc][2], vb[dc][3]);
            }
        }
    }

#pragma unroll
    for (int mt = 0; mt < 4; mt++)
#pragma unroll
        for (int rh = 0; rh < 2; rh++) {
            const int q = mt * 16 + gid + rh * 8;
            __half* orow = octx16 + ((size_t)n * 64 + q) * E + h * 32;
#pragma unroll
            for (int on = 0; on < 4; on++) {
                __half2 o = __float22half2_rn(
                    make_float2(oacc[mt][on][rh * 2 + 0], oacc[mt][on][rh * 2 + 1]));
                *(__half2*)(orow + on * 8 + tig * 2) = o;
            }
        }
}

// ---------------- layer-1 attention ------------------------------------------
__global__ void __launch_bounds__(256) attn1_k(const __half* __restrict__ q1,
                                               const __half* __restrict__ kv1,
                                               __half* __restrict__ o1) {
    const int n = blockIdx.x;
    const int h = threadIdx.x >> 5, l = threadIdx.x & 31;
    __shared__ float qs[256];
    __shared__ float ps[8][64];
    qs[threadIdx.x] = __half2float(q1[(size_t)n * E + threadIdx.x]);
    __syncthreads();

    const __half* kvb = kv1 + (size_t)n * 64 * (2 * E);
    const float* qh  = &qs[h * 32];
    const __half2* k0p = (const __half2*)(kvb + (size_t)l * (2 * E) + h * 32);
    const __half2* k1p = (const __half2*)(kvb + (size_t)(l + 32) * (2 * E) + h * 32);
    float s0 = 0.f, s1 = 0.f;
#pragma unroll
    for (int d = 0; d < 16; d++) {
        const float2 a = __half22float2(k0p[d]);
        const float2 b = __half22float2(k1p[d]);
        s0 = fmaf(qh[2*d], a.x, s0); s0 = fmaf(qh[2*d+1], a.y, s0);
        s1 = fmaf(qh[2*d], b.x, s1); s1 = fmaf(qh[2*d+1], b.y, s1);
    }
    s0 *= ATTN_SCALE; s1 *= ATTN_SCALE;
    float m = fmaxf(s0, s1);
#pragma unroll
    for (int o = 16; o; o >>= 1) m = fmaxf(m, __shfl_xor_sync(0xffffffffu, m, o));
    float e0 = __expf(s0 - m), e1 = __expf(s1 - m);
    float sum = e0 + e1;
#pragma unroll
    for (int o = 16; o; o >>= 1) sum += __shfl_xor_sync(0xffffffffu, sum, o);
    const float inv = 1.f / sum;
    ps[h][l] = e0 * inv;
    ps[h][l + 32] = e1 * inv;
    __syncwarp();

    float acc = 0.f;
#pragma unroll 4
    for (int k = 0; k < 64; k++)
        acc = fmaf(ps[h][k], __half2float(kvb[(size_t)k * (2 * E) + E + h * 32 + l]), acc);
    o1[(size_t)n * E + h * 32 + l] = __float2half(acc);
}

// ---------------- LayerNorm (big-NT path; R12) --------------------------------
__global__ void __launch_bounds__(256) ln_k(const float* __restrict__ X,
                                            const float* __restrict__ g,
                                            const float* __restrict__ bb,
                                            float* __restrict__ Y32,
                                            __half* __restrict__ Y16, int M) {
    const int warp = threadIdx.x >> 5, lane = threadIdx.x & 31;
    const int row = blockIdx.x * 8 + warp;
    if (row >= M) return;
    const float* x = X + (size_t)row * E;
    float2 v[4];
    float s = 0.f;
#pragma unroll
    for (int i = 0; i < 4; i++) {
        v[i] = *(const float2*)(x + 2 * (lane + i * 32));
        s += v[i].x + v[i].y;
    }
#pragma unroll
    for (int o = 16; o; o >>= 1) s += __shfl_xor_sync(0xffffffffu, s, o);
    const float mean = s * (1.f / E);
    float var = 0.f;
#pragma unroll
    for (int i = 0; i < 4; i++) {
        float dx = v[i].x - mean, dy = v[i].y - mean;
        var = fmaf(dx, dx, var); var = fmaf(dy, dy, var);
    }
#pragma unroll
    for (int o = 16; o; o >>= 1) var += __shfl_xor_sync(0xffffffffu, var, o);
    const float inv = rsqrtf(var * (1.f / E) + 1e-5f);
#pragma unroll
    for (int i = 0; i < 4; i++) {
        const int c0 = 2 * (lane + i * 32);
        const float2 gg = *(const float2*)(g + c0);
        const float2 bv = *(const float2*)(bb + c0);
        float y0 = (v[i].x - mean) * inv * gg.x + bv.x;
        float y1 = (v[i].y - mean) * inv * gg.y + bv.y;
        *(float2*)(Y32 + (size_t)row * E + c0) = make_float2(y0, y1);
        *(__half2*)(Y16 + (size_t)row * E + c0) =
            __float22half2_rn(make_float2(y0, y1));
    }
}

// ---------------------------------------------------------------------------
extern "C" void kernel_launch(void* const* d_in, const int* in_sizes, int n_in,
                              void* d_out, int out_size) {
    (void)in_sizes; (void)n_in; (void)out_size;
    const float* inputs     = (const float*)d_in[0];
    const float* embed_w    = (const float*)d_in[1];
    const float* embed_b    = (const float*)d_in[2];
    const float* qkv_w      = (const float*)d_in[3];
    const float* qkv_b      = (const float*)d_in[4];
    const float* attn_out_w = (const float*)d_in[5];
    const float* attn_out_b = (const float*)d_in[6];
    const float* ln1_g      = (const float*)d_in[7];
    const float* ln1_b      = (const float*)d_in[8];
    const float* ffn1_w     = (const float*)d_in[9];
    const float* ffn1_b     = (const float*)d_in[10];
    const float* ffn2_w     = (const float*)d_in[11];
    const float* ffn2_b     = (const float*)d_in[12];
    const float* ln2_g      = (const float*)d_in[13];
    const float* ln2_b      = (const float*)d_in[14];
    const float* head_w     = (const float*)d_in[15];
    const float* head_b     = (const float*)d_in[16];
    float* out = (float*)d_out;

    float *emb32, *x1a, *x1_32, *x2_32, *t1_32, *t2;
    __half *in16, *embw16, *qkvw16, *aow16, *f1w16, *f2w16;
    __half *emb16, *qkv16, *octx16, *x1_16, *h16, *x2_16, *kv16;
    __half *q1_16, *o1_16, *t1_16, *th16;
    cudaGetSymbolAddress((void**)&emb32, g_emb32);
    cudaGetSymbolAddress((void**)&x1a,   g_x1a);
    cudaGetSymbolAddress((void**)&x1_32, g_x1_32);
    cudaGetSymbolAddress((void**)&x2_32, g_x2_32);
    cudaGetSymbolAddress((void**)&t1_32, g_t1_32);
    cudaGetSymbolAddress((void**)&t2,    g_t2);
    cudaGetSymbolAddress((void**)&in16,  g_in16);
    cudaGetSymbolAddress((void**)&embw16,g_embw16);
    cudaGetSymbolAddress((void**)&qkvw16,g_qkvw16);
    cudaGetSymbolAddress((void**)&aow16, g_aow16);
    cudaGetSymbolAddress((void**)&f1w16, g_f1w16);
    cudaGetSymbolAddress((void**)&f2w16, g_f2w16);
    cudaGetSymbolAddress((void**)&emb16, g_emb16);
    cudaGetSymbolAddress((void**)&qkv16, g_qkv16);
    cudaGetSymbolAddress((void**)&octx16,g_octx16);
    cudaGetSymbolAddress((void**)&x1_16, g_x1_16);
    cudaGetSymbolAddress((void**)&h16,   g_h16);
    cudaGetSymbolAddress((void**)&x2_16, g_x2_16);
    cudaGetSymbolAddress((void**)&kv16,  g_kv16);
    cudaGetSymbolAddress((void**)&q1_16, g_q1_16);
    cudaGetSymbolAddress((void**)&o1_16, g_o1_16);
    cudaGetSymbolAddress((void**)&t1_16, g_t1_16);
    cudaGetSymbolAddress((void**)&th16,  g_th16);

    cudaFuncSetAttribute(gemm_h<0,0,1,1>, cudaFuncAttributeMaxDynamicSharedMemorySize, GEMM_SMEM);
    cudaFuncSetAttribute(gemm_h<0,0,0,1>, cudaFuncAttributeMaxDynamicSharedMemorySize, GEMM_SMEM);
    cudaFuncSetAttribute(gemm_h<0,2,1,0>, cudaFuncAttributeMaxDynamicSharedMemorySize, GEMM_SMEM);
    cudaFuncSetAttribute(gemm_h<0,1,1,0>, cudaFuncAttributeMaxDynamicSharedMemorySize, GEMM_SMEM);
    cudaFuncSetAttribute(gemm_h<1,0,0,1>, cudaFuncAttributeMaxDynamicSharedMemorySize, GEMM_SMEM);
    cudaFuncSetAttribute(gemm_ln<1>, cudaFuncAttributeMaxDynamicSharedMemorySize, LN_SMEM);
    cudaFuncSetAttribute(attn0_tc, cudaFuncAttributeMaxDynamicSharedMemorySize, ATT_SMEM);

    // --- (1) all fp32->fp16 conversions in one launch ---
    ConvJobs cj;
    cj.s[0] = inputs;     cj.d[0] = in16;   cj.n[0] = BATCH*SEQ*FIN;
    cj.s[1] = embed_w;    cj.d[1] = embw16; cj.n[1] = E*FIN;
    cj.s[2] = qkv_w;      cj.d[2] = qkvw16; cj.n[2] = 2*3*E*E;
    cj.s[3] = attn_out_w; cj.d[3] = aow16;  cj.n[3] = 2*E*E;
    cj.s[4] = ffn1_w;     cj.d[4] = f1w16;  cj.n[4] = 2*FF*E;
    cj.s[5] = ffn2_w;     cj.d[5] = f2w16;  cj.n[5] = 2*E*FF;
    int convTotal = cj.n[0]+cj.n[1]+cj.n[2]+cj.n[3]+cj.n[4]+cj.n[5];
    conv_all<<<(convTotal + 255)/256, 256>>>(cj);

    // --- (2) zero pad ---
    zero_pad_k<<<63, 256>>>(emb32, emb16);

    // --- (3) embeddings, both batches in one launch (gridDim.z) ---
    gemm_h<0,0,1,1><<<dim3(E/128, SEQ/128, BATCH), 256, GEMM_SMEM>>>(
        in16, FIN, embw16, FIN, embed_b,
        emb32 + (size_t)(WCTX - 1) * E, emb16 + (size_t)(WCTX - 1) * E, E,
        nullptr, 0, SEQ, E, SEQ*FIN, PADS*E);

    // --- (4) layer-0 QKV per global token ---
    gemm_h<0,0,0,1><<<dim3(3*E/128, (BATCH*PADS + 127)/128), 256, GEMM_SMEM>>>(
        emb16, E, qkvw16, E, qkv_b, nullptr, qkv16, 3*E, nullptr, 0,
        BATCH*PADS, 3*E, 0, 0);

    // --- (5) layer-0 attention (tensor cores) ---
    attn0_tc<<<NW, 256, ATT_SMEM>>>(qkv16, octx16);

    // --- (6) layer-0 attn-out + residual gather -> x1a ---
    gemm_h<0,2,1,0><<<dim3(E/128, NT/128), 256, GEMM_SMEM>>>(
        octx16, E, aow16, E, attn_out_b, x1a, nullptr, E, emb32, E, NT, E, 0, 0);
    // --- (7) LN1 ---
    ln_k<<<NT / 8, 256>>>(x1a, ln1_g, ln1_b, x1_32, x1_16, NT);

    // --- (8,9,10) layer-0 FFN + LN2 ---
    gemm_h<1,0,0,1><<<dim3(FF/128, NT/128), 256, GEMM_SMEM>>>(
        x1_16, E, f1w16, E, ffn1_b, nullptr, h16, FF, nullptr, 0, NT, FF, 0, 0);
    gemm_h<0,1,1,0><<<dim3(E/128, NT/128), 256, GEMM_SMEM>>>(
        h16, FF, f2w16, FF, ffn2_b, x1a, nullptr, E, x1_32, E, NT, E, 0, 0);
    ln_k<<<NT / 8, 256>>>(x1a, ln2_g, ln2_b, x2_32, x2_16, NT);

    // --- (11,12) layer-1: K,V all tokens; Q last tokens only ---
    gemm_h<0,0,0,1><<<dim3(2*E/128, NT/128), 256, GEMM_SMEM>>>(
        x2_16, E, qkvw16 + (size_t)3*E*E + (size_t)E*E, E,
        qkv_b + 3*E + E, nullptr, kv16, 2*E, nullptr, 0, NT, 2*E, 0, 0);
    gemm_h<0,0,0,1><<<dim3(E/128, NW/128), 256, GEMM_SMEM>>>(
        x2_16 + (size_t)(WCTX-1)*E, WCTX*E,
        qkvw16 + (size_t)3*E*E, E, qkv_b + 3*E,
        nullptr, q1_16, E, nullptr, 0, NW, E, 0, 0);

    // --- (13) layer-1 attention ---
    attn1_k<<<NW, 256>>>(q1_16, kv16, o1_16);

    // --- (14) tail: attn-out' + residual(last tokens) + LN1' fused ---
    gemm_ln<1><<<NW/64, 256, LN_SMEM>>>(
        o1_16, E, aow16 + (size_t)E*E, E, attn_out_b + E, ln1_g + E, ln1_b + E,
        t1_32, t1_16, x2_32 + (size_t)(WCTX-1)*E, WCTX*E, NW);

    // --- (15) tail FFN1' ---
    gemm_h<1,0,0,1><<<dim3(FF/128, NW/128), 256, GEMM_SMEM>>>(
        t1_16, E, f1w16 + (size_t)FF*E, E, ffn1_b + FF,
        nullptr, th16, FF, nullptr, 0, NW, FF, 0, 0);

    // --- (16) tail FFN2' + residual + LN2' fused -> t2 ---
    gemm_ln<1><<<NW/64, 256, LN_SMEM>>>(
        th16, FF, f2w16 + (size_t)E*FF, FF, ffn2_b + E, ln2_g + E, ln2_b + E,
        t2, o1_16 /*scratch*/, t1_32, E, NW);

    // --- (17) head (N=10, fp32) ---
    gemm_head<<<dim3(1, NW/64), 256>>>(
        t2, E, head_w, E, head_b, out, 10, NW, 10);
}

// round 15
// speedup vs baseline: 1.0717x; 1.0648x over previous
#include <cuda_runtime.h>
#include <cuda_fp16.h>
#include <math.h>
#include <stdint.h>

// ---------------------------------------------------------------------------
// Round 15: all-fp16 activation pipeline. Residuals + pre-LN sums stored fp16
// (LN math stays fp32 in registers): kills emb32/x1a/x1_32/x2_32/t1_32 and
// ~600MB of fp32 HBM traffic. gemm_h gains fp16-residual modes (3=row,
// 4=window gather); new ln16_k (fp16 in -> fp16 out). GEMM cores unchanged.
// ---------------------------------------------------------------------------

#define BATCH 2
#define SEQ   1024
#define E     256
#define FIN   64
#define FF    1024
#define WCTX  64
#define NW    (BATCH*SEQ)
#define PADS  (SEQ + WCTX - 1)
#define NT    (NW*WCTX)

#define ATTN_SCALE 0.17677669529663687f

// ---------------- scratch ----------------------------------------------------
__device__ __align__(128) float g_t2   [NW*E];
__device__ __align__(128) __half g_in16  [BATCH*SEQ*FIN];
__device__ __align__(128) __half g_embw16[E*FIN];
__device__ __align__(128) __half g_qkvw16[2*3*E*E];
__device__ __align__(128) __half g_aow16 [2*E*E];
__device__ __align__(128) __half g_f1w16 [2*FF*E];
__device__ __align__(128) __half g_f2w16 [2*E*FF];
__device__ __align__(128) __half g_emb16 [BATCH*PADS*E];
__device__ __align__(128) __half g_qkv16 [BATCH*PADS*3*E];
__device__ __align__(128) __half g_octx16[NT*E];
__device__ __align__(128) __half g_pre16 [NT*E];
__device__ __align__(128) __half g_x1_16 [NT*E];
__device__ __align__(128) __half g_h16   [NT*FF];
__device__ __align__(128) __half g_x2_16 [NT*E];
__device__ __align__(128) __half g_kv16  [NT*2*E];
__device__ __align__(128) __half g_q1_16 [NW*E];
__device__ __align__(128) __half g_o1_16 [NW*E];
__device__ __align__(128) __half g_t1_16 [NW*E];
__device__ __align__(128) __half g_th16  [NW*FF];

// ---------------- fused fp32->fp16 conversion (one launch) --------------------
struct ConvJobs {
    const float* s[6];
    __half* d[6];
    int n[6];
};
__global__ void conv_all(ConvJobs j) {
    int idx = blockIdx.x * 256 + threadIdx.x;
#pragma unroll
    for (int k = 0; k < 6; k++) {
        if (idx < j.n[k]) { j.d[k][idx] = __float2half(j.s[k][idx]); return; }
        idx -= j.n[k];
    }
}

__global__ void zero_pad_k(__half* emb16) {
    int i = blockIdx.x * 256 + threadIdx.x;
    if (i < (WCTX - 1) * E) {
        emb16[i] = __float2half(0.f);
        emb16[(size_t)PADS * E + i] = __float2half(0.f);
    }
}

// ---------------- shared MMA / ldmatrix macros --------------------------------
#define MMA_F16(d, a0, a1, a2, a3, b0, b1) \
  asm volatile("mma.sync.aligned.m16n8k16.row.col.f32.f16.f16.f32 " \
    "{%0,%1,%2,%3}, {%4,%5,%6,%7}, {%8,%9}, {%0,%1,%2,%3};" \
    : "+f"(d[0]), "+f"(d[1]), "+f"(d[2]), "+f"(d[3]) \
    : "r"(a0), "r"(a1), "r"(a2), "r"(a3), "r"(b0), "r"(b1))

#define LDSM_X4(r0, r1, r2, r3, ad) \
  asm volatile("ldmatrix.sync.aligned.m8n8.x4.shared.b16 {%0,%1,%2,%3}, [%4];" \
    : "=r"(r0), "=r"(r1), "=r"(r2), "=r"(r3) : "r"(ad))

#define LDSM_X4T(r0, r1, r2, r3, ad) \
  asm volatile("ldmatrix.sync.aligned.m8n8.x4.trans.shared.b16 {%0,%1,%2,%3}, [%4];" \
    : "=r"(r0), "=r"(r1), "=r"(r2), "=r"(r3) : "r"(ad))

// ---------------- fp16 tensor-core GEMM ---------------------------------------
#define T_TSB 16384
#define NSTG 3
#define GEMM_SMEM (2*NSTG*T_TSB)

#define LOAD_TILE(KT_IDX, ST) do {                                            \
    if ((KT_IDX) < KT) {                                                      \
        const unsigned abase_ = smbase + (unsigned)(ST) * T_TSB;              \
        const unsigned bbase_ = smbase + (unsigned)NSTG * T_TSB + (unsigned)(ST) * T_TSB; \
        const __half* Ak_ = A + (size_t)(KT_IDX) * 64;                        \
        const __half* Bk_ = Wt + (size_t)(KT_IDX) * 64;                       \
        _Pragma("unroll")                                                     \
        for (int i_ = 0; i_ < 4; i_++) {                                      \
            const int c_   = tid + 256 * i_;                                  \
            const int row_ = c_ >> 3;                                         \
            const int ch_  = c_ & 7;                                          \
            const unsigned soff_ = (unsigned)(row_ * 128 + ((ch_ ^ (row_ & 7)) * 16)); \
            const int am_  = bm0 + row_;                                      \
            const __half* sa_ = Ak_ + (size_t)(am_ < M ? am_ : 0) * lda + ch_ * 8; \
            const int sz_     = (am_ < M) ? 16 : 0;                           \
            asm volatile("cp.async.cg.shared.global [%0], [%1], 16, %2;" ::   \
                "r"(abase_ + soff_), "l"(sa_), "r"(sz_));                     \
            const __half* sb_ = Bk_ + (size_t)(bn0 + row_) * K + ch_ * 8;     \
            asm volatile("cp.async.cg.shared.global [%0], [%1], 16;" ::       \
                "r"(bbase_ + soff_), "l"(sb_));                               \
        }                                                                     \
    }                                                                         \
    asm volatile("cp.async.commit_group;");                                   \
} while (0)

#define COMPUTE_TILE(ST) do {                                                 \
    const unsigned abase_ = smbase + (unsigned)(ST) * T_TSB;                  \
    const unsigned bbase_ = smbase + (unsigned)NSTG * T_TSB + (unsigned)(ST) * T_TSB; \
    _Pragma("unroll")                                                         \
    for (int kk_ = 0; kk_ < 4; kk_++) {                                       \
        const int chl_ = 2 * kk_ + (lane >> 4);                               \
        unsigned Ar[4][4];                                                    \
        unsigned Br[2][4];                                                    \
        _Pragma("unroll")                                                     \
        for (int mt_ = 0; mt_ < 4; mt_++) {                                   \
            const int r_ = wm + mt_ * 16 + (lane & 15);                       \
            LDSM_X4(Ar[mt_][0], Ar[mt_][1], Ar[mt_][2], Ar[mt_][3],           \
                    abase_ + (unsigned)(r_ * 128 + ((chl_ ^ (r_ & 7)) * 16)));\
        }                                                                     \
        _Pragma("unroll")                                                     \
        for (int np_ = 0; np_ < 2; np_++) {                                   \
            const int r_ = wn + np_ * 16 + (lane & 15);                       \
            LDSM_X4(Br[np_][0], Br[np_][1], Br[np_][2], Br[np_][3],           \
                    bbase_ + (unsigned)(r_ * 128 + ((chl_ ^ (r_ & 7)) * 16)));\
        }                                                                     \
        _Pragma("unroll")                                                     \
        for (int mt_ = 0; mt_ < 4; mt_++)                                     \
            _Pragma("unroll")                                                 \
            for (int np_ = 0; np_ < 2; np_++) {                               \
                MMA_F16(acc[mt_][np_ * 2 + 0], Ar[mt_][0], Ar[mt_][1],        \
                        Ar[mt_][2], Ar[mt_][3], Br[np_][0], Br[np_][2]);      \
                MMA_F16(acc[mt_][np_ * 2 + 1], Ar[mt_][0], Ar[mt_][1],        \
                        Ar[mt_][2], Ar[mt_][3], Br[np_][1], Br[np_][3]);      \
            }                                                                 \
    }                                                                         \
} while (0)

// RES: 0 none, 3 fp16 row residual, 4 fp16 window-gather residual.
template<int ACT, int RES, int O32, int O16>
__global__ void __launch_bounds__(256, 2) gemm_h(
    const __half* __restrict__ A, int lda,
    const __half* __restrict__ Wt, int K,
    const float* __restrict__ bias,
    float* __restrict__ C32, __half* __restrict__ C16, int ldc,
    const __half* __restrict__ res16, int ldres,
    int M, int N, int zA, int zC)
{
    extern __shared__ __half smh[];
    const int tid  = threadIdx.x;
    const int bm0  = blockIdx.y * 128;
    const int bn0  = blockIdx.x * 128;
    const int lane = tid & 31, warp = tid >> 5;
    const int wm = (warp & 1) * 64;
    const int wn = (warp >> 1) * 32;
    const int gid = lane >> 2, tig = lane & 3;

    A += (size_t)blockIdx.z * (size_t)zA;
    const size_t coff = (size_t)blockIdx.z * (size_t)zC;
    if (O32) C32 += coff;
    if (O16) C16 += coff;

    const unsigned smbase = (unsigned)__cvta_generic_to_shared(smh);

    float acc[4][4][4];
#pragma unroll
    for (int i = 0; i < 4; i++)
#pragma unroll
        for (int j = 0; j < 4; j++)
#pragma unroll
            for (int r = 0; r < 4; r++) acc[i][j][r] = 0.f;

    const int KT = K >> 6;

    LOAD_TILE(0, 0);
    LOAD_TILE(1, 1);

    for (int kt = 0; kt < KT; kt++) {
        asm volatile("cp.async.wait_group 1;");
        __syncthreads();
        LOAD_TILE(kt + 2, (kt + 2) % 3);
        COMPUTE_TILE(kt % 3);
    }

#pragma unroll
    for (int mt = 0; mt < 4; mt++) {
        const int mbase = bm0 + wm + mt * 16 + gid;
#pragma unroll
        for (int half_ = 0; half_ < 2; half_++) {
            const int m = mbase + half_ * 8;
            if (m >= M) continue;
#pragma unroll
            for (int nt = 0; nt < 4; nt++) {
                const int n = bn0 + wn + nt * 8 + tig * 2;
                const float2 bv = *(const float2*)(bias + n);
                float v0 = acc[mt][nt][half_ * 2 + 0] + bv.x;
                float v1 = acc[mt][nt][half_ * 2 + 1] + bv.y;
                if (RES == 3) {
                    const float2 r = __half22float2(
                        *(const __half2*)(res16 + (size_t)m * ldres + n));
                    v0 += r.x; v1 += r.y;
                }
                if (RES == 4) {
                    const int nw = m >> 6, w = m & 63;
                    const int b = nw >> 10, s = nw & 1023;
                    const float2 r = __half22float2(*(const __half2*)(
                        res16 + ((size_t)(b * PADS + s + w)) * ldres + n));
                    v0 += r.x; v1 += r.y;
                }
                if (ACT == 1) {
                    v0 = v0 / (1.f + __expf(-v0));
                    v1 = v1 / (1.f + __expf(-v1));
                }
                if (O32)
                    *(float2*)(C32 + (size_t)m * ldc + n) = make_float2(v0, v1);
                if (O16)
                    *(__half2*)(C16 + (size_t)m * ldc + n) =
                        __float22half2_rn(make_float2(v0, v1));
            }
        }
    }
}

// ---------------- fused GEMM + LayerNorm (tail; fp16 residual) ----------------
#define LN_A_TSB 4096
#define LN_B_TSB 16384
#define LN_NSTG 4
#define LN_SMEM (LN_NSTG*(LN_A_TSB+LN_B_TSB))

#define LOAD_LN(CH, ST) do {                                                  \
    if ((CH) < KT) {                                                          \
        const unsigned abase_ = smbase + (unsigned)(ST) * LN_A_TSB;           \
        const unsigned bbase_ = smbase + (unsigned)LN_NSTG * LN_A_TSB         \
                                + (unsigned)(ST) * LN_B_TSB;                  \
        const __half* Ak_ = A + (size_t)(CH) * 32;                            \
        const __half* Bk_ = Wt + (size_t)(CH) * 32;                           \
        {                                                                     \
            const int row_ = tid >> 2, ch_ = tid & 3;                         \
            const __half* sa_ = Ak_ + (size_t)(bm0 + row_) * lda + ch_ * 8;   \
            asm volatile("cp.async.cg.shared.global [%0], [%1], 16;" ::       \
                "r"(abase_ + (unsigned)(row_ * 64 + ((ch_ ^ (row_ & 3)) * 16))), \
                "l"(sa_));                                                    \
        }                                                                     \
        _Pragma("unroll")                                                     \
        for (int i_ = 0; i_ < 4; i_++) {                                      \
            const int c_ = tid + 256 * i_;                                    \
            const int row_ = c_ >> 2, ch_ = c_ & 3;                           \
            const __half* sb_ = Bk_ + (size_t)row_ * K + ch_ * 8;             \
            asm volatile("cp.async.cg.shared.global [%0], [%1], 16;" ::       \
                "r"(bbase_ + (unsigned)(row_ * 64 + ((ch_ ^ (row_ & 3)) * 16))), \
                "l"(sb_));                                                    \
        }                                                                     \
    }                                                                         \
    asm volatile("cp.async.commit_group;");                                   \
} while (0)

#define COMPUTE_LN(ST) do {                                                   \
    const unsigned abase_ = smbase + (unsigned)(ST) * LN_A_TSB;               \
    const unsigned bbase_ = smbase + (unsigned)LN_NSTG * LN_A_TSB             \
                            + (unsigned)(ST) * LN_B_TSB;                      \
    _Pragma("unroll")                                                         \
    for (int kk_ = 0; kk_ < 2; kk_++) {                                       \
        const int chl_ = 2 * kk_ + (lane >> 4);                               \
        unsigned Ar[2][4];                                                    \
        unsigned Br[4][4];                                                    \
        _Pragma("unroll")                                                     \
        for (int mt_ = 0; mt_ < 2; mt_++) {                                   \
            const int r_ = wm + mt_ * 16 + (lane & 15);                       \
            LDSM_X4(Ar[mt_][0], Ar[mt_][1], Ar[mt_][2], Ar[mt_][3],           \
                    abase_ + (unsigned)(r_ * 64 + ((chl_ ^ (r_ & 3)) * 16))); \
        }                                                                     \
        _Pragma("unroll")                                                     \
        for (int np_ = 0; np_ < 4; np_++) {                                   \
            const int r_ = wn + np_ * 16 + (lane & 15);                       \
            LDSM_X4(Br[np_][0], Br[np_][1], Br[np_][2], Br[np_][3],           \
                    bbase_ + (unsigned)(r_ * 64 + ((chl_ ^ (r_ & 3)) * 16))); \
        }                                                                     \
        _Pragma("unroll")                                                     \
        for (int mt_ = 0; mt_ < 2; mt_++)                                     \
            _Pragma("unroll")                                                 \
            for (int np_ = 0; np_ < 4; np_++) {                               \
                MMA_F16(acc[mt_][np_ * 2 + 0], Ar[mt_][0], Ar[mt_][1],        \
                        Ar[mt_][2], Ar[mt_][3], Br[np_][0], Br[np_][2]);      \
                MMA_F16(acc[mt_][np_ * 2 + 1], Ar[mt_][0], Ar[mt_][1],        \
                        Ar[mt_][2], Ar[mt_][3], Br[np_][1], Br[np_][3]);      \
            }                                                                 \
    }                                                                         \
} while (0)

template<int O32>
__global__ void __launch_bounds__(256, 2) gemm_ln(
    const __half* __restrict__ A, int lda,
    const __half* __restrict__ Wt, int K,
    const float* __restrict__ bias,
    const float* __restrict__ lng, const float* __restrict__ lnb,
    float* __restrict__ Y32, __half* __restrict__ Y16,
    const __half* __restrict__ res16, int ldres, int M)
{
    extern __shared__ __half smh[];
    const int tid  = threadIdx.x;
    const int bm0  = blockIdx.x * 64;
    const int lane = tid & 31, warp = tid >> 5;
    const int wm = (warp & 1) * 32;
    const int wn = (warp >> 1) * 64;
    const int gid = lane >> 2, tig = lane & 3;
    const int ng = warp >> 1;
    (void)M;

    const unsigned smbase = (unsigned)__cvta_generic_to_shared(smh);

    float acc[2][8][4];
#pragma unroll
    for (int i = 0; i < 2; i++)
#pragma unroll
        for (int j = 0; j < 8; j++)
#pragma unroll
            for (int r = 0; r < 4; r++) acc[i][j][r] = 0.f;

    const int KT = K >> 5;

    LOAD_LN(0, 0);
    LOAD_LN(1, 1);
    LOAD_LN(2, 2);

    for (int kt = 0; kt < KT; kt++) {
        asm volatile("cp.async.wait_group 2;");
        __syncthreads();
        LOAD_LN(kt + 3, (kt + 3) & 3);
        COMPUTE_LN(kt & 3);
    }

    __syncthreads();

#pragma unroll
    for (int mt = 0; mt < 2; mt++)
#pragma unroll
        for (int nt = 0; nt < 8; nt++) {
            const int n = wn + nt * 8 + tig * 2;
            const float2 bv = *(const float2*)(bias + n);
#pragma unroll
            for (int rh = 0; rh < 2; rh++) {
                const int m = bm0 + wm + mt * 16 + gid + rh * 8;
                const float2 r = __half22float2(
                    *(const __half2*)(res16 + (size_t)m * ldres + n));
                acc[mt][nt][rh * 2 + 0] += bv.x + r.x;
                acc[mt][nt][rh * 2 + 1] += bv.y + r.y;
            }
        }

    float* red = (float*)smh;
    float mean_[2][2], rstd_[2][2];

#pragma unroll
    for (int mt = 0; mt < 2; mt++)
#pragma unroll
        for (int rh = 0; rh < 2; rh++) {
            float s = 0.f;
#pragma unroll
            for (int nt = 0; nt < 8; nt++)
                s += acc[mt][nt][rh * 2] + acc[mt][nt][rh * 2 + 1];
            s += __shfl_xor_sync(0xffffffffu, s, 1);
            s += __shfl_xor_sync(0xffffffffu, s, 2);
            const int lr = wm + mt * 16 + gid + rh * 8;
            if (tig == 0) red[lr * 4 + ng] = s;
        }
    __syncthreads();
#pragma unroll
    for (int mt = 0; mt < 2; mt++)
#pragma unroll
        for (int rh = 0; rh < 2; rh++) {
            const int lr = wm + mt * 16 + gid + rh * 8;
            mean_[mt][rh] = (red[lr * 4] + red[lr * 4 + 1] +
                             red[lr * 4 + 2] + red[lr * 4 + 3]) * (1.f / 256.f);
        }

#pragma unroll
    for (int mt = 0; mt < 2; mt++)
#pragma unroll
        for (int rh = 0; rh < 2; rh++) {
            float v = 0.f;
#pragma unroll
            for (int nt = 0; nt < 8; nt++) {
                float d0 = acc[mt][nt][rh * 2 + 0] - mean_[mt][rh];
                float d1 = acc[mt][nt][rh * 2 + 1] - mean_[mt][rh];
                v = fmaf(d0, d0, v);
                v = fmaf(d1, d1, v);
            }
            v += __shfl_xor_sync(0xffffffffu, v, 1);
            v += __shfl_xor_sync(0xffffffffu, v, 2);
            const int lr = wm + mt * 16 + gid + rh * 8;
            if (tig == 0) red[256 + lr * 4 + ng] = v;
        }
    __syncthreads();
#pragma unroll
    for (int mt = 0; mt < 2; mt++)
#pragma unroll
        for (int rh = 0; rh < 2; rh++) {
            const int lr = wm + mt * 16 + gid + rh * 8;
            float v = red[256 + lr * 4] + red[256 + lr * 4 + 1] +
                      red[256 + lr * 4 + 2] + red[256 + lr * 4 + 3];
            rstd_[mt][rh] = rsqrtf(v * (1.f / 256.f) + 1e-5f);
        }

#pragma unroll
    for (int mt = 0; mt < 2; mt++)
#pragma unroll
        for (int nt = 0; nt < 8; nt++) {
            const int n = wn + nt * 8 + tig * 2;
            const float2 gg = *(const float2*)(lng + n);
            const float2 b2 = *(const float2*)(lnb + n);
#pragma unroll
            for (int rh = 0; rh < 2; rh++) {
                const int m = bm0 + wm + mt * 16 + gid + rh * 8;
                float y0 = (acc[mt][nt][rh * 2 + 0] - mean_[mt][rh]) * rstd_[mt][rh] * gg.x + b2.x;
                float y1 = (acc[mt][nt][rh * 2 + 1] - mean_[mt][rh]) * rstd_[mt][rh] * gg.y + b2.y;
                if (O32)
                    *(float2*)(Y32 + (size_t)m * 256 + n) = make_float2(y0, y1);
                *(__half2*)(Y16 + (size_t)m * 256 + n) =
                    __float22half2_rn(make_float2(y0, y1));
            }
        }
}

// ---------------- small fp32 GEMM (head only, N=10) --------------------------
__global__ void __launch_bounds__(256) gemm_head(
    const float* __restrict__ A, int lda,
    const float* __restrict__ Wt, int K,
    const float* __restrict__ bias,
    float* __restrict__ C, int ldc, int M, int N)
{
    __shared__ float As[16][68];
    __shared__ float Bs[16][68];
    const int tid = threadIdx.x;
    const int m0 = blockIdx.y * 64;
    const int lr = tid >> 2;
    const int lc = (tid & 3) << 2;
    const int ty = tid >> 4;
    const int tx = tid & 15;

    float acc[4][4];
#pragma unroll
    for (int i = 0; i < 4; i++)
#pragma unroll
        for (int j = 0; j < 4; j++) acc[i][j] = 0.f;

    const int am = m0 + lr;
    const float* Aptr = A + (size_t)am * lda + lc;
    const float* Wptr = Wt + (size_t)lr * K + lc;
    const bool avalid = (am < M);
    const bool bvalid = (lr < N);

    for (int k0 = 0; k0 < K; k0 += 16) {
        float4 av = make_float4(0.f, 0.f, 0.f, 0.f);
        float4 bv = make_float4(0.f, 0.f, 0.f, 0.f);
        if (avalid) av = *(const float4*)(Aptr + k0);
        if (bvalid) bv = *(const float4*)(Wptr + k0);
        As[lc+0][lr] = av.x; As[lc+1][lr] = av.y;
        As[lc+2][lr] = av.z; As[lc+3][lr] = av.w;
        Bs[lc+0][lr] = bv.x; Bs[lc+1][lr] = bv.y;
        Bs[lc+2][lr] = bv.z; Bs[lc+3][lr] = bv.w;
        __syncthreads();
#pragma unroll
        for (int kk = 0; kk < 16; kk++) {
            float4 a4 = *(const float4*)&As[kk][ty << 2];
            float4 b4 = *(const float4*)&Bs[kk][tx << 2];
            float ar[4] = {a4.x, a4.y, a4.z, a4.w};
            float br[4] = {b4.x, b4.y, b4.z, b4.w};
#pragma unroll
            for (int i = 0; i < 4; i++)
#pragma unroll
                for (int j = 0; j < 4; j++)
                    acc[i][j] = fmaf(ar[i], br[j], acc[i][j]);
        }
        __syncthreads();
    }

#pragma unroll
    for (int i = 0; i < 4; i++) {
        int m = m0 + (ty << 2) + i;
        if (m >= M) continue;
#pragma unroll
        for (int j = 0; j < 4; j++) {
            int n = (tx << 2) + j;
            if (n >= N) continue;
            C[(size_t)m * ldc + n] = acc[i][j] + bias[n];
        }
    }
}

// ---------------- tensor-core layer-0 attention (R12, unchanged) --------------
#define ATT_STR 776
#define ATT_SMEM (64*ATT_STR*2)

__global__ void __launch_bounds__(256) attn0_tc(const __half* __restrict__ qkv16,
                                                __half* __restrict__ octx16) {
    extern __shared__ __half sma[];
    const unsigned smb = (unsigned)__cvta_generic_to_shared(sma);
    const int n = blockIdx.x, b = n >> 10, s = n & 1023;
    const int tid = threadIdx.x, lane = tid & 31, h = tid >> 5;
    const int gid = lane >> 2, tig = lane & 3;
    const int lrow = lane & 15, lch = lane >> 4;

#pragma unroll
    for (int i = 0; i < 24; i++) {
        const int c = tid + 256 * i;
        const int row = c / 96, ch = c - row * 96;
        const __half* src = qkv16 + (size_t)(b * PADS + s + row) * 768 + ch * 8;
        asm volatile("cp.async.cg.shared.global [%0], [%1], 16;" ::
            "r"(smb + (unsigned)((row * ATT_STR + ch * 8) * 2)), "l"(src));
    }
    asm volatile("cp.async.commit_group;");
    asm volatile("cp.async.wait_group 0;");
    __syncthreads();

    float sacc[4][8][4];
#pragma unroll
    for (int i = 0; i < 4; i++)
#pragma unroll
        for (int j = 0; j < 8; j++)
#pragma unroll
            for (int r = 0; r < 4; r++) sacc[i][j][r] = 0.f;

#pragma unroll
    for (int kk = 0; kk < 2; kk++) {
        unsigned qa[4][4], kb[4][4];
        const int kcol = h * 32 + kk * 16 + lch * 8;
#pragma unroll
        for (int mt = 0; mt < 4; mt++)
            LDSM_X4(qa[mt][0], qa[mt][1], qa[mt][2], qa[mt][3],
                    smb + (unsigned)(((mt * 16 + lrow) * ATT_STR + kcol) * 2));
#pragma unroll
        for (int kt = 0; kt < 4; kt++)
            LDSM_X4(kb[kt][0], kb[kt][1], kb[kt][2], kb[kt][3],
                    smb + (unsigned)(((kt * 16 + lrow) * ATT_STR + 256 + kcol) * 2));
#pragma unroll
        for (int mt = 0; mt < 4; mt++)
#pragma unroll
            for (int kt = 0; kt < 4; kt++) {
                MMA_F16(sacc[mt][kt * 2 + 0], qa[mt][0], qa[mt][1], qa[mt][2], qa[mt][3],
                        kb[kt][0], kb[kt][2]);
                MMA_F16(sacc[mt][kt * 2 + 1], qa[mt][0], qa[mt][1], qa[mt][2], qa[mt][3],
                        kb[kt][1], kb[kt][3]);
            }
    }

#pragma unroll
    for (int mt = 0; mt < 4; mt++)
#pragma unroll
        for (int rh = 0; rh < 2; rh++) {
            float mx = -1e30f;
#pragma unroll
            for (int nt = 0; nt < 8; nt++)
                mx = fmaxf(mx, fmaxf(sacc[mt][nt][rh * 2], sacc[mt][nt][rh * 2 + 1]));
            mx = fmaxf(mx, __shfl_xor_sync(0xffffffffu, mx, 1));
            mx = fmaxf(mx, __shfl_xor_sync(0xffffffffu, mx, 2));
            float sum = 0.f;
#pragma unroll
            for (int nt = 0; nt < 8; nt++) {
                float e0 = __expf((sacc[mt][nt][rh * 2 + 0] - mx) * ATTN_SCALE);
                float e1 = __expf((sacc[mt][nt][rh * 2 + 1] - mx) * ATTN_SCALE);
                sacc[mt][nt][rh * 2 + 0] = e0;
                sacc[mt][nt][rh * 2 + 1] = e1;
                sum += e0 + e1;
            }
            sum += __shfl_xor_sync(0xffffffffu, sum, 1);
            sum += __shfl_xor_sync(0xffffffffu, sum, 2);
            const float inv = 1.f / sum;
#pragma unroll
            for (int nt = 0; nt < 8; nt++) {
                sacc[mt][nt][rh * 2 + 0] *= inv;
                sacc[mt][nt][rh * 2 + 1] *= inv;
            }
        }

    float oacc[4][4][4];
#pragma unroll
    for (int i = 0; i < 4; i++)
#pragma unroll
        for (int j = 0; j < 4; j++)
#pragma unroll
            for (int r = 0; r < 4; r++) oacc[i][j][r] = 0.f;

#pragma unroll
    for (int j = 0; j < 4; j++) {
        unsigned vb[2][4];
#pragma unroll
        for (int dc = 0; dc < 2; dc++)
            LDSM_X4T(vb[dc][0], vb[dc][1], vb[dc][2], vb[dc][3],
                     smb + (unsigned)(((j * 16 + lrow) * ATT_STR + 512 + h * 32
                                       + dc * 16 + lch * 8) * 2));
#pragma unroll
        for (int mt = 0; mt < 4; mt++) {
            __half2 h0 = __float22half2_rn(make_float2(sacc[mt][2*j][0],   sacc[mt][2*j][1]));
            __half2 h1 = __float22half2_rn(make_float2(sacc[mt][2*j][2],   sacc[mt][2*j][3]));
            __half2 h2 = __float22half2_rn(make_float2(sacc[mt][2*j+1][0], sacc[mt][2*j+1][1]));
            __half2 h3 = __float22half2_rn(make_float2(sacc[mt][2*j+1][2], sacc[mt][2*j+1][3]));
            const unsigned a0 = *(unsigned*)&h0, a1 = *(unsigned*)&h1;
            const unsigned a2 = *(unsigned*)&h2, a3 = *(unsigned*)&h3;
#pragma unroll
            for (int dc = 0; dc < 2; dc++) {
                MMA_F16(oacc[mt][dc * 2 + 0], a0, a1, a2, a3, vb[dc][0], vb[dc][1]);
                MMA_F16(oacc[mt][dc * 2 + 1], a0, a1, a2, a3, vb[dc][2], vb[dc][3]);
            }
        }
    }

#pragma unroll
    for (int mt = 0; mt < 4; mt++)
#pragma unroll
        for (int rh = 0; rh < 2; rh++) {
            const int q = mt * 16 + gid + rh * 8;
            __half* orow = octx16 + ((size_t)n * 64 + q) * E + h * 32;
#pragma unroll
            for (int on = 0; on < 4; on++) {
                __half2 o = __float22half2_rn(
                    make_float2(oacc[mt][on][rh * 2 + 0], oacc[mt][on][rh * 2 + 1]));
                *(__half2*)(orow + on * 8 + tig * 2) = o;
            }
        }
}

// ---------------- layer-1 attention ------------------------------------------
__global__ void __launch_bounds__(256) attn1_k(const __half* __restrict__ q1,
                                               const __half* __restrict__ kv1,
                                               __half* __restrict__ o1) {
    const int n = blockIdx.x;
    const int h = threadIdx.x >> 5, l = threadIdx.x & 31;
    __shared__ float qs[256];
    __shared__ float ps[8][64];
    qs[threadIdx.x] = __half2float(q1[(size_t)n * E + threadIdx.x]);
    __syncthreads();

    const __half* kvb = kv1 + (size_t)n * 64 * (2 * E);
    const float* qh  = &qs[h * 32];
    const __half2* k0p = (const __half2*)(kvb + (size_t)l * (2 * E) + h * 32);
    const __half2* k1p = (const __half2*)(kvb + (size_t)(l + 32) * (2 * E) + h * 32);
    float s0 = 0.f, s1 = 0.f;
#pragma unroll
    for (int d = 0; d < 16; d++) {
        const float2 a = __half22float2(k0p[d]);
        const float2 b = __half22float2(k1p[d]);
        s0 = fmaf(qh[2*d], a.x, s0); s0 = fmaf(qh[2*d+1], a.y, s0);
        s1 = fmaf(qh[2*d], b.x, s1); s1 = fmaf(qh[2*d+1], b.y, s1);
    }
    s0 *= ATTN_SCALE; s1 *= ATTN_SCALE;
    float m = fmaxf(s0, s1);
#pragma unroll
    for (int o = 16; o; o >>= 1) m = fmaxf(m, __shfl_xor_sync(0xffffffffu, m, o));
    float e0 = __expf(s0 - m), e1 = __expf(s1 - m);
    float sum = e0 + e1;
#pragma unroll
    for (int o = 16; o; o >>= 1) sum += __shfl_xor_sync(0xffffffffu, sum, o);
    const float inv = 1.f / sum;
    ps[h][l] = e0 * inv;
    ps[h][l + 32] = e1 * inv;
    __syncwarp();

    float acc = 0.f;
#pragma unroll 4
    for (int k = 0; k < 64; k++)
        acc = fmaf(ps[h][k], __half2float(kvb[(size_t)k * (2 * E) + E + h * 32 + l]), acc);
    o1[(size_t)n * E + h * 32 + l] = __float2half(acc);
}

// ---------------- LayerNorm: fp16 in -> fp16 out (fp32 math) ------------------
__global__ void __launch_bounds__(256) ln16_k(const __half* __restrict__ X,
                                              const float* __restrict__ g,
                                              const float* __restrict__ bb,
                                              __half* __restrict__ Y, int M) {
    const int warp = threadIdx.x >> 5, lane = threadIdx.x & 31;
    const int row = blockIdx.x * 8 + warp;
    if (row >= M) return;
    const __half2* x = (const __half2*)(X + (size_t)row * E);
    float2 v[4];
    float s = 0.f;
#pragma unroll
    for (int i = 0; i < 4; i++) {
        v[i] = __half22float2(x[lane + i * 32]);
        s += v[i].x + v[i].y;
    }
#pragma unroll
    for (int o = 16; o; o >>= 1) s += __shfl_xor_sync(0xffffffffu, s, o);
    const float mean = s * (1.f / E);
    float var = 0.f;
#pragma unroll
    for (int i = 0; i < 4; i++) {
        float dx = v[i].x - mean, dy = v[i].y - mean;
        var = fmaf(dx, dx, var); var = fmaf(dy, dy, var);
    }
#pragma unroll
    for (int o = 16; o; o >>= 1) var += __shfl_xor_sync(0xffffffffu, var, o);
    const float inv = rsqrtf(var * (1.f / E) + 1e-5f);
    __half2* y = (__half2*)(Y + (size_t)row * E);
#pragma unroll
    for (int i = 0; i < 4; i++) {
        const int c0 = 2 * (lane + i * 32);
        const float2 gg = *(const float2*)(g + c0);
        const float2 bv = *(const float2*)(bb + c0);
        float y0 = (v[i].x - mean) * inv * gg.x + bv.x;
        float y1 = (v[i].y - mean) * inv * gg.y + bv.y;
        y[lane + i * 32] = __float22half2_rn(make_float2(y0, y1));
    }
}

// ---------------------------------------------------------------------------
extern "C" void kernel_launch(void* const* d_in, const int* in_sizes, int n_in,
                              void* d_out, int out_size) {
    (void)in_sizes; (void)n_in; (void)out_size;
    const float* inputs     = (const float*)d_in[0];
    const float* embed_w    = (const float*)d_in[1];
    const float* embed_b    = (const float*)d_in[2];
    const float* qkv_w      = (const float*)d_in[3];
    const float* qkv_b      = (const float*)d_in[4];
    const float* attn_out_w = (const float*)d_in[5];
    const float* attn_out_b = (const float*)d_in[6];
    const float* ln1_g      = (const float*)d_in[7];
    const float* ln1_b      = (const float*)d_in[8];
    const float* ffn1_w     = (const float*)d_in[9];
    const float* ffn1_b     = (const float*)d_in[10];
    const float* ffn2_w     = (const float*)d_in[11];
    const float* ffn2_b     = (const float*)d_in[12];
    const float* ln2_g      = (const float*)d_in[13];
    const float* ln2_b      = (const float*)d_in[14];
    const float* head_w     = (const float*)d_in[15];
    const float* head_b     = (const float*)d_in[16];
    float* out = (float*)d_out;

    float *t2;
    __half *in16, *embw16, *qkvw16, *aow16, *f1w16, *f2w16;
    __half *emb16, *qkv16, *octx16, *pre16, *x1_16, *h16, *x2_16, *kv16;
    __half *q1_16, *o1_16, *t1_16, *th16;
    cudaGetSymbolAddress((void**)&t2,    g_t2);
    cudaGetSymbolAddress((void**)&in16,  g_in16);
    cudaGetSymbolAddress((void**)&embw16,g_embw16);
    cudaGetSymbolAddress((void**)&qkvw16,g_qkvw16);
    cudaGetSymbolAddress((void**)&aow16, g_aow16);
    cudaGetSymbolAddress((void**)&f1w16, g_f1w16);
    cudaGetSymbolAddress((void**)&f2w16, g_f2w16);
    cudaGetSymbolAddress((void**)&emb16, g_emb16);
    cudaGetSymbolAddress((void**)&qkv16, g_qkv16);
    cudaGetSymbolAddress((void**)&octx16,g_octx16);
    cudaGetSymbolAddress((void**)&pre16, g_pre16);
    cudaGetSymbolAddress((void**)&x1_16, g_x1_16);
    cudaGetSymbolAddress((void**)&h16,   g_h16);
    cudaGetSymbolAddress((void**)&x2_16, g_x2_16);
    cudaGetSymbolAddress((void**)&kv16,  g_kv16);
    cudaGetSymbolAddress((void**)&q1_16, g_q1_16);
    cudaGetSymbolAddress((void**)&o1_16, g_o1_16);
    cudaGetSymbolAddress((void**)&t1_16, g_t1_16);
    cudaGetSymbolAddress((void**)&th16,  g_th16);

    cudaFuncSetAttribute(gemm_h<0,0,0,1>, cudaFuncAttributeMaxDynamicSharedMemorySize, GEMM_SMEM);
    cudaFuncSetAttribute(gemm_h<0,4,0,1>, cudaFuncAttributeMaxDynamicSharedMemorySize, GEMM_SMEM);
    cudaFuncSetAttribute(gemm_h<0,3,0,1>, cudaFuncAttributeMaxDynamicSharedMemorySize, GEMM_SMEM);
    cudaFuncSetAttribute(gemm_h<1,0,0,1>, cudaFuncAttributeMaxDynamicSharedMemorySize, GEMM_SMEM);
    cudaFuncSetAttribute(gemm_ln<0>, cudaFuncAttributeMaxDynamicSharedMemorySize, LN_SMEM);
    cudaFuncSetAttribute(gemm_ln<1>, cudaFuncAttributeMaxDynamicSharedMemorySize, LN_SMEM);
    cudaFuncSetAttribute(attn0_tc, cudaFuncAttributeMaxDynamicSharedMemorySize, ATT_SMEM);

    // --- (1) all fp32->fp16 conversions in one launch ---
    ConvJobs cj;
    cj.s[0] = inputs;     cj.d[0] = in16;   cj.n[0] = BATCH*SEQ*FIN;
    cj.s[1] = embed_w;    cj.d[1] = embw16; cj.n[1] = E*FIN;
    cj.s[2] = qkv_w;      cj.d[2] = qkvw16; cj.n[2] = 2*3*E*E;
    cj.s[3] = attn_out_w; cj.d[3] = aow16;  cj.n[3] = 2*E*E;
    cj.s[4] = ffn1_w;     cj.d[4] = f1w16;  cj.n[4] = 2*FF*E;
    cj.s[5] = ffn2_w;     cj.d[5] = f2w16;  cj.n[5] = 2*E*FF;
    int convTotal = cj.n[0]+cj.n[1]+cj.n[2]+cj.n[3]+cj.n[4]+cj.n[5];
    conv_all<<<(convTotal + 255)/256, 256>>>(cj);

    // --- (2) zero pad ---
    zero_pad_k<<<63, 256>>>(emb16);

    // --- (3) embeddings, both batches in one launch ---
    gemm_h<0,0,0,1><<<dim3(E/128, SEQ/128, BATCH), 256, GEMM_SMEM>>>(
        in16, FIN, embw16, FIN, embed_b,
        nullptr, emb16 + (size_t)(WCTX - 1) * E, E,
        nullptr, 0, SEQ, E, SEQ*FIN, PADS*E);

    // --- (4) layer-0 QKV per global token ---
    gemm_h<0,0,0,1><<<dim3(3*E/128, (BATCH*PADS + 127)/128), 256, GEMM_SMEM>>>(
        emb16, E, qkvw16, E, qkv_b, nullptr, qkv16, 3*E, nullptr, 0,
        BATCH*PADS, 3*E, 0, 0);

    // --- (5) layer-0 attention ---
    attn0_tc<<<NW, 256, ATT_SMEM>>>(qkv16, octx16);

    // --- (6) attn-out + fp16 residual gather -> pre16 ---
    gemm_h<0,4,0,1><<<dim3(E/128, NT/128), 256, GEMM_SMEM>>>(
        octx16, E, aow16, E, attn_out_b, nullptr, pre16, E, emb16, E, NT, E, 0, 0);
    // --- (7) LN1 (fp16 -> fp16) ---
    ln16_k<<<NT / 8, 256>>>(pre16, ln1_g, ln1_b, x1_16, NT);

    // --- (8,9,10) layer-0 FFN + LN2 ---
    gemm_h<1,0,0,1><<<dim3(FF/128, NT/128), 256, GEMM_SMEM>>>(
        x1_16, E, f1w16, E, ffn1_b, nullptr, h16, FF, nullptr, 0, NT, FF, 0, 0);
    gemm_h<0,3,0,1><<<dim3(E/128, NT/128), 256, GEMM_SMEM>>>(
        h16, FF, f2w16, FF, ffn2_b, nullptr, pre16, E, x1_16, E, NT, E, 0, 0);
    ln16_k<<<NT / 8, 256>>>(pre16, ln2_g, ln2_b, x2_16, NT);

    // --- (11,12) layer-1: K,V all tokens; Q last tokens only ---
    gemm_h<0,0,0,1><<<dim3(2*E/128, NT/128), 256, GEMM_SMEM>>>(
        x2_16, E, qkvw16 + (size_t)3*E*E + (size_t)E*E, E,
        qkv_b + 3*E + E, nullptr, kv16, 2*E, nullptr, 0, NT, 2*E, 0, 0);
    gemm_h<0,0,0,1><<<dim3(E/128, NW/128), 256, GEMM_SMEM>>>(
        x2_16 + (size_t)(WCTX-1)*E, WCTX*E,
        qkvw16 + (size_t)3*E*E, E, qkv_b + 3*E,
        nullptr, q1_16, E, nullptr, 0, NW, E, 0, 0);

    // --- (13) layer-1 attention ---
    attn1_k<<<NW, 256>>>(q1_16, kv16, o1_16);

    // --- (14) tail: attn-out' + fp16 residual (last tokens) + LN1' fused ---
    gemm_ln<0><<<NW/64, 256, LN_SMEM>>>(
        o1_16, E, aow16 + (size_t)E*E, E, attn_out_b + E, ln1_g + E, ln1_b + E,
        nullptr, t1_16, x2_16 + (size_t)(WCTX-1)*E, WCTX*E, NW);

    // --- (15) tail FFN1' ---
    gemm_h<1,0,0,1><<<dim3(FF/128, NW/128), 256, GEMM_SMEM>>>(
        t1_16, E, f1w16 + (size_t)FF*E, E, ffn1_b + FF,
        nullptr, th16, FF, nullptr, 0, NW, FF, 0, 0);

    // --- (16) tail FFN2' + fp16 residual + LN2' fused -> t2 (fp32 for head) ---
    gemm_ln<1><<<NW/64, 256, LN_SMEM>>>(
        th16, FF, f2w16 + (size_t)E*FF, FF, ffn2_b + E, ln2_g + E, ln2_b + E,
        t2, o1_16 /*scratch*/, t1_16, E, NW);

    // --- (17) head (N=10, fp32) ---
    gemm_head<<<dim3(1, NW/64), 256>>>(
        t2, E, head_w, E, head_b, out, 10, NW, 10);
}